// round 4
// baseline (speedup 1.0000x reference)
#include <cuda_runtime.h>
#include <cuda_bf16.h>
#include <math.h>

#define DEV __device__ __forceinline__

constexpr int   NN   = 8192;
constexpr int   HH   = 128;
constexpr float KPC  = -1.f;   // Poincare
constexpr float KSC  =  1.f;   // Sphere
constexpr float EPSV = 1e-6f;

// ======================= warp / vector helpers =======================
DEV float wsum(float v) {
#pragma unroll
    for (int o = 16; o; o >>= 1) v += __shfl_xor_sync(0xffffffffu, v, o);
    return v;
}
template <int V> DEV float vdot(const float* a, const float* b) {
    float s = 0.f;
#pragma unroll
    for (int t = 0; t < V; t++) s = fmaf(a[t], b[t], s);
    return wsum(s);
}
template <int V> DEV float vnorm2(const float* a) { return vdot<V>(a, a); }
DEV float safe_n(float n2) { return sqrtf(n2 + 1e-15f); }

DEV float tank(float u, float k) {
    if (k < 0.f) return tanhf(u);
    u = fminf(fmaxf(u, -1.47079f), 1.47079f);
    return tanf(u);
}
DEV float artank(float u, float k) {
    if (k < 0.f) {
        u = fminf(fmaxf(u, -1.f + 1e-5f), 1.f - 1e-5f);
        return atanhf(u);
    }
    return atanf(u);
}
DEV float sigf(float x) { return 1.f / (1.f + __expf(-x)); }
DEV float sdn(float d) { return (d >= 0.f) ? fmaxf(d, EPSV) : fminf(d, -EPSV); }

template <int V> DEV void projv(float* x, float k) {
    if (k < 0.f) {
        float n = safe_n(vnorm2<V>(x));
        float m = 1.f - 1e-4f;
        float s = (n > m) ? (m / n) : 1.f;
#pragma unroll
        for (int t = 0; t < V; t++) x[t] *= s;
    }
}
template <int V> DEV void expmap0v(float* o, const float* u, float k) {
    float n = safe_n(vnorm2<V>(u));
    float s = tank(n, k) / n;
#pragma unroll
    for (int t = 0; t < V; t++) o[t] = s * u[t];
    projv<V>(o, k);
}
template <int V> DEV void logmap0v(float* o, const float* y, float k) {
    float n = safe_n(vnorm2<V>(y));
    float s = artank(n, k) / n;
#pragma unroll
    for (int t = 0; t < V; t++) o[t] = s * y[t];
}
template <int V> DEV void maddv(float* o, const float* x, const float* y, float k) {
    float x2 = vnorm2<V>(x), y2 = vnorm2<V>(y), xy = vdot<V>(x, y);
    float A = 1.f - 2.f * k * xy - k * y2;
    float B = 1.f + k * x2;
    float den = 1.f - 2.f * k * xy + k * k * x2 * y2;
    float inv = 1.f / sdn(den);
#pragma unroll
    for (int t = 0; t < V; t++) o[t] = (A * x[t] + B * y[t]) * inv;
    projv<V>(o, k);
}
template <int V> DEV void pwmulv(float* o, const float* w, const float* x, float k) {
    float wx[V];
#pragma unroll
    for (int t = 0; t < V; t++) wx[t] = w[t] * x[t];
    float nx  = safe_n(vnorm2<V>(x));
    float nwx = safe_n(vnorm2<V>(wx));
    float s = tank(nwx / nx * artank(nx, k), k) / nwx;
#pragma unroll
    for (int t = 0; t < V; t++) o[t] = s * wx[t];
    projv<V>(o, k);
}
// mobius_pw_mul(w_vec, g_scalar_broadcast, k): x has last-dim size 1 in ref
template <int V> DEV void pwscalv(float* o, const float* w, float g, float k) {
    float wx[V];
#pragma unroll
    for (int t = 0; t < V; t++) wx[t] = w[t] * g;
    float nx  = sqrtf(g * g + 1e-15f);
    float nwx = safe_n(vnorm2<V>(wx));
    float s = tank(nwx / nx * artank(nx, k), k) / nwx;
#pragma unroll
    for (int t = 0; t < V; t++) o[t] = s * wx[t];
    projv<V>(o, k);
}
template <int V> DEV void smulv(float* o, float r, const float* x, float k) {
    float n = safe_n(vnorm2<V>(x));
    float s = tank(r * artank(n, k), k) / n;
#pragma unroll
    for (int t = 0; t < V; t++) o[t] = s * x[t];
    projv<V>(o, k);
}
template <int V> DEV void wmid3v(float* o, const float* a, const float* b,
                                 const float* c, float k) {
    float la = 2.f / (1.f + k * vnorm2<V>(a));
    float lb = 2.f / (1.f + k * vnorm2<V>(b));
    float lc = 2.f / (1.f + k * vnorm2<V>(c));
    float den = fabsf(la + lb + lc - 3.f);
    float inv = 1.f / fmaxf(den, EPSV);
    float tmp[V];
#pragma unroll
    for (int t = 0; t < V; t++) tmp[t] = (la * a[t] + lb * b[t] + lc * c[t]) * inv;
    smulv<V>(o, 0.5f, tmp, k);
}

DEV void load4(float* v, const float* p, int lane) {
#pragma unroll
    for (int t = 0; t < 4; t++) v[t] = p[lane + 32 * t];
}
DEV void store4(float* p, const float* v, int lane) {
#pragma unroll
    for (int t = 0; t < 4; t++) p[lane + 32 * t] = v[t];
}
DEV void load12(float* v, const float* p, int lane) {
#pragma unroll
    for (int t = 0; t < 12; t++) v[t] = p[lane + 32 * t];
}

// dist(x,y,k) = 2*artan_k(||proj(mobius_add(-x,y,k))||).  p = dot(x,y).
DEV float distk(float x2, float y2, float p, float k) {
    float A = 1.f + 2.f * k * p - k * y2;     // coeff of (-x)
    float B = 1.f + k * x2;                   // coeff of y
    float den = 1.f + 2.f * k * p + k * k * x2 * y2;
    float nd = sdn(den);
    float q2 = fmaxf(A * A * x2 - 2.f * A * B * p + B * B * y2, 0.f) / (nd * nd);
    if (k < 0.f) {
        float n = sqrtf(q2 + 1e-15f);
        float m = 1.f - 1e-4f;
        if (n > m) { float s = m / n; q2 *= s * s; }
        float nf = sqrtf(q2 + 1e-15f);
        nf = fminf(nf, 1.f - 1e-5f);
        return 2.f * atanhf(nf);
    }
    float nf = sqrtf(q2 + 1e-15f);
    return 2.f * atanf(nf);
}

DEV void softmax8(const float* s, float* a) {
    float m = s[0];
#pragma unroll
    for (int q = 1; q < 8; q++) m = fmaxf(m, s[q]);
    float sum = 0.f;
#pragma unroll
    for (int q = 0; q < 8; q++) { a[q] = __expf(s[q] - m); sum += a[q]; }
    float inv = 1.f / sum;
#pragma unroll
    for (int q = 0; q < 8; q++) a[q] *= inv;
}

// ======================= device scratch =======================
__device__ float g_Lh1[NN * HH], g_Lh2[NN * HH], g_Lc1[NN * HH], g_Lc2[NN * HH];
__device__ float g_XPm[NN * HH], g_XSm[NN * HH];
__device__ float g_Yup1[NN * HH], g_Yup2[NN * HH], g_Yup3[NN * HH];
__device__ float g_Yc1[NN * HH],  g_Yc2[NN * HH],  g_Yc3[NN * HH];
__device__ float g_Yuf1[NN * HH], g_Yuf2[NN * HH], g_Yuf3[NN * HH];
__device__ float g_XQP[NN * HH],  g_XQS[NN * HH],  g_XQE[NN * HH];
__device__ float g_HP[NN * HH], g_HS[NN * HH], g_HE[NN * HH];
__device__ float g_CP[NN * HH], g_CS[NN * HH], g_CE[NN * HH];
__device__ float g_X1P[NN * HH], g_X1S[NN * HH];
__device__ float g_TP[NN * HH], g_TS[NN * HH], g_TE[NN * HH];
__device__ float g_C1[NN * HH], g_C2[NN * HH], g_C3[NN * HH];
__device__ float g_Zp[NN * 384], g_Zs[NN * 384], g_Ze[NN * 384];
__device__ float g_y2P[NN], g_y2S[NN], g_c2P[NN], g_c2S[NN], g_x2P[NN], g_x2S[NN];

// ======================= S0: logmap prep =======================
__global__ __launch_bounds__(256) void s0_prep(const float* __restrict__ x,
                                               const float* __restrict__ h1,
                                               const float* __restrict__ h2,
                                               const float* __restrict__ c1,
                                               const float* __restrict__ c2) {
    int n = (blockIdx.x * 256 + threadIdx.x) >> 5;
    if (n >= NN) return;
    int lane = threadIdx.x & 31;
    size_t off = (size_t)n * HH;
    float v[4], e[4], o[4];
    load4(v, x + off, lane);
    expmap0v<4>(e, v, KPC); logmap0v<4>(o, e, KPC); store4(g_XPm + off, o, lane);
    expmap0v<4>(e, v, KSC); logmap0v<4>(o, e, KSC); store4(g_XSm + off, o, lane);
    load4(v, h1 + off, lane); logmap0v<4>(o, v, KPC); store4(g_Lh1 + off, o, lane);
    load4(v, h2 + off, lane); logmap0v<4>(o, v, KSC); store4(g_Lh2 + off, o, lane);
    load4(v, c1 + off, lane); logmap0v<4>(o, v, KPC); store4(g_Lc1 + off, o, lane);
    load4(v, c2 + off, lane); logmap0v<4>(o, v, KSC); store4(g_Lc2 + off, o, lane);
}

// ======================= batched GEMM: C = A @ W^T + b =======================
// A: [8192,128] rm, W: [NO,128] rm, C: [8192,NO]. 64x64 tile, 256 thr, 4x4 micro.
struct GemmDesc { const float* A; const float* W; const float* bias; float* C; };
struct GemmBatch { GemmDesc p[12]; };

__global__ __launch_bounds__(256) void gemm_k(GemmBatch gb, int NO) {
    __shared__ __align__(16) float As[32][68];
    __shared__ __align__(16) float Ws[32][68];
    GemmDesc d = gb.p[blockIdx.z];
    int m0 = blockIdx.x * 64, n0 = blockIdx.y * 64;
    int tx = threadIdx.x;
    int mg = tx >> 4, ng = tx & 15;
    float acc[4][4] = {};
#pragma unroll
    for (int k0 = 0; k0 < 128; k0 += 32) {
#pragma unroll
        for (int i = 0; i < 2; i++) {
            int t2 = tx + i * 256;
            int r = t2 >> 3, kc = (t2 & 7) * 4;
            float4 va = *(const float4*)&d.A[(size_t)(m0 + r) * 128 + k0 + kc];
            As[kc + 0][r] = va.x; As[kc + 1][r] = va.y;
            As[kc + 2][r] = va.z; As[kc + 3][r] = va.w;
            float4 vw = *(const float4*)&d.W[(size_t)(n0 + r) * 128 + k0 + kc];
            Ws[kc + 0][r] = vw.x; Ws[kc + 1][r] = vw.y;
            Ws[kc + 2][r] = vw.z; Ws[kc + 3][r] = vw.w;
        }
        __syncthreads();
#pragma unroll
        for (int k = 0; k < 32; k++) {
            float4 a = *(const float4*)&As[k][mg * 4];
            float4 w = *(const float4*)&Ws[k][ng * 4];
            float av[4] = {a.x, a.y, a.z, a.w};
            float wv[4] = {w.x, w.y, w.z, w.w};
#pragma unroll
            for (int i = 0; i < 4; i++)
#pragma unroll
                for (int j = 0; j < 4; j++) acc[i][j] = fmaf(av[i], wv[j], acc[i][j]);
        }
        __syncthreads();
    }
#pragma unroll
    for (int i = 0; i < 4; i++) {
        size_t row = (size_t)(m0 + mg * 4 + i) * NO;
#pragma unroll
        for (int j = 0; j < 4; j++) {
            int col = n0 + ng * 4 + j;
            d.C[row + col] = acc[i][j] + d.bias[col];
        }
    }
}

// ======================= S2: per-source-node stage =======================
__global__ __launch_bounds__(256) void s2_node(const float* __restrict__ h1,
                                               const float* __restrict__ h2,
                                               const float* __restrict__ h3,
                                               const float* __restrict__ c1,
                                               const float* __restrict__ c2,
                                               const float* __restrict__ c3,
                                               const float* __restrict__ del_t,
                                               const float* __restrict__ dscal) {
    int n = (blockIdx.x * 256 + threadIdx.x) >> 5;
    if (n >= NN) return;
    int lane = threadIdx.x & 31;
    size_t off = (size_t)n * HH;

    float mh1[4], mh2[4], mh3[4], lh1[4], lh2[4];
    load4(mh1, h1 + off, lane);
    load4(mh2, h2 + off, lane);
    load4(mh3, h3 + off, lane);
    load4(lh1, g_Lh1 + off, lane);
    load4(lh2, g_Lh2 + off, lane);

    float t[4], e[4], s1[4], s2v[4], s3v[4];
    load4(t, g_Yup1 + off, lane);
    expmap0v<4>(e, t, KPC);
#pragma unroll
    for (int i = 0; i < 4; i++) e[i] = sigf(e[i]);
    logmap0v<4>(s1, e, KPC);
    load4(t, g_Yup2 + off, lane);
    expmap0v<4>(e, t, KSC);
#pragma unroll
    for (int i = 0; i < 4; i++) e[i] = sigf(e[i]);
    logmap0v<4>(s2v, e, KSC);
    load4(t, g_Yup3 + off, lane);
#pragma unroll
    for (int i = 0; i < 4; i++) s3v[i] = sigf(t[i]);

    // ---- h_1p ----
    float ht1p[4], ht2p[4], ht3p[4], tmp[4], HP[4];
    pwmulv<4>(ht1p, s1, mh1, KPC);
    expmap0v<4>(tmp, lh2, KPC); pwmulv<4>(ht2p, s2v, tmp, KPC);
    expmap0v<4>(tmp, mh3, KPC); pwmulv<4>(ht3p, s3v, tmp, KPC);
    wmid3v<4>(HP, ht1p, ht2p, ht3p, KPC);
#pragma unroll
    for (int i = 0; i < 4; i++) HP[i] *= 3.f;
    store4(g_HP + off, HP, lane);
    float y2p = vnorm2<4>(HP);
    if (lane == 0) g_y2P[n] = y2p;

    // ---- h_1s ----
    float ht1s[4], ht2s[4], ht3s[4], HS[4];
    expmap0v<4>(tmp, lh1, KSC); pwmulv<4>(ht1s, s1, tmp, KPC);
    pwmulv<4>(ht2s, s2v, mh2, KSC);
    expmap0v<4>(tmp, mh3, KSC); pwmulv<4>(ht3s, s3v, tmp, KSC);
    wmid3v<4>(HS, ht1s, ht2s, ht3s, KPC);
#pragma unroll
    for (int i = 0; i < 4; i++) HS[i] *= 3.f;
    store4(g_HS + off, HS, lane);
    float y2s = vnorm2<4>(HS);
    if (lane == 0) g_y2S[n] = y2s;

    // ---- h_1e ----
    float he[4], l1[4], l2[4];
    logmap0v<4>(l1, ht1p, KPC);
    logmap0v<4>(l2, ht2s, KSC);
#pragma unroll
    for (int i = 0; i < 4; i++) he[i] = l1[i] + l2[i] + s3v[i] * mh3[i];
    store4(g_HE + off, he, lane);

    float g = dscal[0] / (del_t[n] + 1.f);

    // ---- Poincare cell ----
    {
        float mc[4]; load4(mc, c1 + off, lane);
        load4(t, g_Yc1 + off, lane);
        expmap0v<4>(e, t, KPC); logmap0v<4>(t, e, KPC);
#pragma unroll
        for (int i = 0; i < 4; i++) t[i] = tanhf(t[i]);
        float csk[4]; expmap0v<4>(csk, t, KPC);
        float pw[4]; pwscalv<4>(pw, csk, g, KPC);
        float neg[4];
#pragma unroll
        for (int i = 0; i < 4; i++) neg[i] = -csk[i];
        float m1[4]; maddv<4>(m1, neg, mc, KPC);
        float ckt[4]; maddv<4>(ckt, m1, pw, KPC);
        load4(t, g_Yuf1 + off, lane);
        expmap0v<4>(e, t, KPC); logmap0v<4>(t, e, KPC);
        float f[4];
#pragma unroll
        for (int i = 0; i < 4; i++) f[i] = sigf(t[i]);
        float CP[4]; pwmulv<4>(CP, f, ckt, KPC);
        store4(g_CP + off, CP, lane);
        float c2p = vnorm2<4>(CP);
        if (lane == 0) g_c2P[n] = c2p;
    }
    // ---- Sphere cell ----
    {
        float mc[4]; load4(mc, c2 + off, lane);
        load4(t, g_Yc2 + off, lane);
        expmap0v<4>(e, t, KSC); logmap0v<4>(t, e, KSC);
#pragma unroll
        for (int i = 0; i < 4; i++) t[i] = tanhf(t[i]);
        float csk[4]; expmap0v<4>(csk, t, KSC);
        float pw[4]; pwscalv<4>(pw, csk, g, KSC);
        float neg[4];
#pragma unroll
        for (int i = 0; i < 4; i++) neg[i] = -csk[i];
        float m1[4]; maddv<4>(m1, neg, mc, KSC);
        float ckt[4]; maddv<4>(ckt, m1, pw, KSC);
        load4(t, g_Yuf2 + off, lane);
        expmap0v<4>(e, t, KSC); logmap0v<4>(t, e, KSC);
        float f[4];
#pragma unroll
        for (int i = 0; i < 4; i++) f[i] = sigf(t[i]);
        float CS[4]; pwmulv<4>(CS, f, ckt, KSC);
        store4(g_CS + off, CS, lane);
        float c2s = vnorm2<4>(CS);
        if (lane == 0) g_c2S[n] = c2s;
    }
    // ---- Euclidean cell ----
    {
        float mc[4]; load4(mc, c3 + off, lane);
        load4(t, g_Yc3 + off, lane);
        float CE[4];
#pragma unroll
        for (int i = 0; i < 4; i++) {
            float csk = tanhf(t[i]);
            CE[i] = mc[i] - csk + csk * g;
        }
        load4(t, g_Yuf3 + off, lane);
#pragma unroll
        for (int i = 0; i < 4; i++) CE[i] *= sigf(t[i]);
        store4(g_CE + off, CE, lane);
    }
    // ---- dest-side queries ----
    {
        float q[4];
        load4(t, g_XQP + off, lane);
        expmap0v<4>(q, t, KPC);
        store4(g_X1P + off, q, lane);
        float x2 = vnorm2<4>(q);
        if (lane == 0) g_x2P[n] = x2;
        load4(t, g_XQS + off, lane);
        expmap0v<4>(q, t, KSC);
        store4(g_X1S + off, q, lane);
        x2 = vnorm2<4>(q);
        if (lane == 0) g_x2S[n] = x2;
    }
}

// ======================= S3: gather + attention + midpoints =======================
DEV void attn_hyp(size_t off, const int* jarr, const float* Xq, const float* x2t,
                  const float* Htab, const float* y2t, float kcur,
                  float* outT, int n, int lane) {
    float xq[4]; load4(xq, Xq + off, lane);
    float x2 = x2t[n];
    float vh[8][4], y2r[8], sc[8], a[8];
#pragma unroll
    for (int k = 0; k < 8; k++) {
        int j = jarr[k];
        load4(vh[k], Htab + (size_t)j * HH, lane);
        y2r[k] = y2t[j];
        float p = vdot<4>(xq, vh[k]);
        sc[k] = -distk(x2, y2r[k], p, kcur);
    }
    softmax8(sc, a);
    float num[4] = {0, 0, 0, 0};
    float ds = 0.f;
#pragma unroll
    for (int k = 0; k < 8; k++) {
        float lam = 2.f / (1.f + kcur * y2r[k]);
#pragma unroll
        for (int t = 0; t < 4; t++) num[t] = fmaf(a[k] * lam, vh[k][t], num[t]);
        ds += a[k] * (lam - 1.f);
    }
    float inv = 1.f / fmaxf(fabsf(ds), EPSV);
    float r[4];
#pragma unroll
    for (int t = 0; t < 4; t++) r[t] = num[t] * inv;
    float ht[4]; smulv<4>(ht, 0.5f, r, kcur);
    float lt[4]; logmap0v<4>(lt, ht, kcur);
    store4(outT + off, lt, lane);
}

DEV void cellmid(size_t off, const int* jarr, const float* Ctab, const float* c2t,
                 float kcur, float* outC, int lane) {
    float num[4] = {0, 0, 0, 0};
    float ds = 0.f;
#pragma unroll
    for (int k = 0; k < 8; k++) {
        int j = jarr[k];
        float cv[4]; load4(cv, Ctab + (size_t)j * HH, lane);
        float lam = 2.f / (1.f + kcur * c2t[j]);
#pragma unroll
        for (int t = 0; t < 4; t++) num[t] = fmaf(lam, cv[t], num[t]);
        ds += lam - 1.f;
    }
    float inv = 1.f / fmaxf(fabsf(ds), EPSV);
    float r[4];
#pragma unroll
    for (int t = 0; t < 4; t++) r[t] = num[t] * inv;
    float o[4]; smulv<4>(o, 0.5f, r, kcur);
    store4(outC + off, o, lane);
}

__global__ __launch_bounds__(256) void s3_attn(const int* __restrict__ nbr) {
    int n = (blockIdx.x * 256 + threadIdx.x) >> 5;
    if (n >= NN) return;
    int lane = threadIdx.x & 31;
    size_t off = (size_t)n * HH;
    int jarr[8];
#pragma unroll
    for (int k = 0; k < 8; k++) jarr[k] = nbr[n * 8 + k];

    attn_hyp(off, jarr, g_X1P, g_x2P, g_HP, g_y2P, KPC, g_TP, n, lane);
    attn_hyp(off, jarr, g_X1S, g_x2S, g_HS, g_y2S, KSC, g_TS, n, lane);

    // Euclidean attention
    {
        float xq[4]; load4(xq, g_XQE + off, lane);
        float vh[8][4], sc[8], a[8];
#pragma unroll
        for (int k = 0; k < 8; k++) {
            load4(vh[k], g_HE + (size_t)jarr[k] * HH, lane);
            sc[k] = vdot<4>(xq, vh[k]) * 0.08838834764831845f;  // 1/sqrt(128)
        }
        softmax8(sc, a);
        float he[4] = {0, 0, 0, 0};
#pragma unroll
        for (int k = 0; k < 8; k++)
#pragma unroll
            for (int t = 0; t < 4; t++) he[t] = fmaf(a[k], vh[k][t], he[t]);
        store4(g_TE + off, he, lane);
    }

    cellmid(off, jarr, g_CP, g_c2P, KPC, g_C1, lane);
    cellmid(off, jarr, g_CS, g_c2S, KSC, g_C2, lane);

    // c_3 = sum_k CE(j)
    {
        float s[4] = {0, 0, 0, 0};
#pragma unroll
        for (int k = 0; k < 8; k++) {
            float cv[4]; load4(cv, g_CE + (size_t)jarr[k] * HH, lane);
#pragma unroll
            for (int t = 0; t < 4; t++) s[t] += cv[t];
        }
        store4(g_C3 + off, s, lane);
    }
}

// ======================= S5: final node update =======================
__global__ __launch_bounds__(128) void s5_final(const float* __restrict__ iou1,
                                                const float* __restrict__ iou2,
                                                const float* __restrict__ iou3,
                                                float* __restrict__ out) {
    int n = (blockIdx.x * 128 + threadIdx.x) >> 5;
    if (n >= NN) return;
    int lane = threadIdx.x & 31;
    size_t o384 = (size_t)n * 384, o128 = (size_t)n * HH;
    const size_t SL = (size_t)NN * HH;

    // ---- Poincare ----
    {
        float z[12], e[12], io[12], ni[12];
        load12(z, g_Zp + o384, lane);
        expmap0v<12>(e, z, KPC);
        load12(io, iou1 + o384, lane);
        maddv<12>(ni, io, e, KPC);
        float ip[4], op[4], up[4];
        logmap0v<4>(ip, ni + 0, KPC);
        logmap0v<4>(op, ni + 4, KPC);
        logmap0v<4>(up, ni + 8, KPC);
#pragma unroll
        for (int i = 0; i < 4; i++) { ip[i] = sigf(ip[i]); op[i] = sigf(op[i]); up[i] = tanhf(up[i]); }
        float pu[4]; pwmulv<4>(pu, ip, up, KPC);
        float cv[4]; load4(cv, g_C1 + o128, lane);
        float nc[4]; maddv<4>(nc, pu, cv, KPC);
        float lg[4]; logmap0v<4>(lg, nc, KPC);
#pragma unroll
        for (int i = 0; i < 4; i++) lg[i] = tanhf(lg[i]);
        float nh[4]; pwmulv<4>(nh, op, lg, KPC);
        store4(out + 0 * SL + o128, nh, lane);
        store4(out + 1 * SL + o128, nc, lane);
    }
    // ---- Sphere ----
    {
        float z[12], e[12], io[12], ni[12];
        load12(z, g_Zs + o384, lane);
        expmap0v<12>(e, z, KSC);
        load12(io, iou2 + o384, lane);
        maddv<12>(ni, io, e, KSC);
        float ip[4], op[4], up[4];
        logmap0v<4>(ip, ni + 0, KSC);
        logmap0v<4>(op, ni + 4, KSC);
        logmap0v<4>(up, ni + 8, KSC);
#pragma unroll
        for (int i = 0; i < 4; i++) { ip[i] = sigf(ip[i]); op[i] = sigf(op[i]); up[i] = tanhf(up[i]); }
        float pu[4]; pwmulv<4>(pu, ip, up, KSC);
        float cv[4]; load4(cv, g_C2 + o128, lane);
        float nc[4]; maddv<4>(nc, pu, cv, KSC);
        float lg[4]; logmap0v<4>(lg, nc, KSC);
#pragma unroll
        for (int i = 0; i < 4; i++) lg[i] = tanhf(lg[i]);
        float nh[4]; pwmulv<4>(nh, op, lg, KSC);
        store4(out + 2 * SL + o128, nh, lane);
        store4(out + 3 * SL + o128, nc, lane);
    }
    // ---- Euclidean ----
    {
        float z[12], io[12];
        load12(z, g_Ze + o384, lane);
        load12(io, iou3 + o384, lane);
        float cv[4]; load4(cv, g_C3 + o128, lane);
        float nc[4], nh[4];
#pragma unroll
        for (int i = 0; i < 4; i++) {
            float ie = sigf(io[i] + z[i]);
            float oe = sigf(io[i + 4] + z[i + 4]);
            float ue = tanhf(io[i + 8] + z[i + 8]);
            nc[i] = ie * ue + cv[i];
            nh[i] = oe * tanhf(nc[i]);
        }
        store4(out + 4 * SL + o128, nh, lane);
        store4(out + 5 * SL + o128, nc, lane);
    }
}

// ======================= launch =======================
extern "C" void kernel_launch(void* const* d_in, const int* in_sizes, int n_in,
                              void* d_out, int out_size) {
    const float* x     = (const float*)d_in[0];
    const float* h1    = (const float*)d_in[1];
    const float* c1    = (const float*)d_in[2];
    const float* h2    = (const float*)d_in[3];
    const float* c2    = (const float*)d_in[4];
    const float* h3    = (const float*)d_in[5];
    const float* c3    = (const float*)d_in[6];
    const float* del_t = (const float*)d_in[7];
    const float* iou1  = (const float*)d_in[8];
    const float* iou2  = (const float*)d_in[9];
    const float* iou3  = (const float*)d_in[10];
    const float* Wq_w  = (const float*)d_in[11];
    const float* Wq_b  = (const float*)d_in[12];
    const float* Wc_w  = (const float*)d_in[13];
    const float* Wc_b  = (const float*)d_in[14];
    const float* Uf_w  = (const float*)d_in[15];
    const float* Uf_b  = (const float*)d_in[16];
    const float* Up_w  = (const float*)d_in[17];
    const float* Up_b  = (const float*)d_in[18];
    const float* Uiou_w = (const float*)d_in[19];
    const float* Uiou_b = (const float*)d_in[20];
    const float* dsc   = (const float*)d_in[21];
    const int*   nbr   = (const int*)d_in[22];
    float* out = (float*)d_out;

    float *pLh1, *pLh2, *pLc1, *pLc2, *pXPm, *pXSm;
    float *pYup1, *pYup2, *pYup3, *pYc1, *pYc2, *pYc3, *pYuf1, *pYuf2, *pYuf3;
    float *pXQP, *pXQS, *pXQE, *pTP, *pTS, *pTE, *pZp, *pZs, *pZe;
    cudaGetSymbolAddress((void**)&pLh1, g_Lh1);
    cudaGetSymbolAddress((void**)&pLh2, g_Lh2);
    cudaGetSymbolAddress((void**)&pLc1, g_Lc1);
    cudaGetSymbolAddress((void**)&pLc2, g_Lc2);
    cudaGetSymbolAddress((void**)&pXPm, g_XPm);
    cudaGetSymbolAddress((void**)&pXSm, g_XSm);
    cudaGetSymbolAddress((void**)&pYup1, g_Yup1);
    cudaGetSymbolAddress((void**)&pYup2, g_Yup2);
    cudaGetSymbolAddress((void**)&pYup3, g_Yup3);
    cudaGetSymbolAddress((void**)&pYc1, g_Yc1);
    cudaGetSymbolAddress((void**)&pYc2, g_Yc2);
    cudaGetSymbolAddress((void**)&pYc3, g_Yc3);
    cudaGetSymbolAddress((void**)&pYuf1, g_Yuf1);
    cudaGetSymbolAddress((void**)&pYuf2, g_Yuf2);
    cudaGetSymbolAddress((void**)&pYuf3, g_Yuf3);
    cudaGetSymbolAddress((void**)&pXQP, g_XQP);
    cudaGetSymbolAddress((void**)&pXQS, g_XQS);
    cudaGetSymbolAddress((void**)&pXQE, g_XQE);
    cudaGetSymbolAddress((void**)&pTP, g_TP);
    cudaGetSymbolAddress((void**)&pTS, g_TS);
    cudaGetSymbolAddress((void**)&pTE, g_TE);
    cudaGetSymbolAddress((void**)&pZp, g_Zp);
    cudaGetSymbolAddress((void**)&pZs, g_Zs);
    cudaGetSymbolAddress((void**)&pZe, g_Ze);

    s0_prep<<<NN / 8, 256>>>(x, h1, h2, c1, c2);

    GemmBatch ga;
    ga.p[0]  = {pLh1, Up_w, Up_b, pYup1};
    ga.p[1]  = {pLh2, Up_w, Up_b, pYup2};
    ga.p[2]  = {h3,   Up_w, Up_b, pYup3};
    ga.p[3]  = {pLc1, Wc_w, Wc_b, pYc1};
    ga.p[4]  = {pLc2, Wc_w, Wc_b, pYc2};
    ga.p[5]  = {c3,   Wc_w, Wc_b, pYc3};
    ga.p[6]  = {pLh1, Uf_w, Uf_b, pYuf1};
    ga.p[7]  = {pLh2, Uf_w, Uf_b, pYuf2};
    ga.p[8]  = {h3,   Uf_w, Uf_b, pYuf3};
    ga.p[9]  = {pXPm, Wq_w, Wq_b, pXQP};
    ga.p[10] = {pXSm, Wq_w, Wq_b, pXQS};
    ga.p[11] = {x,    Wq_w, Wq_b, pXQE};
    gemm_k<<<dim3(NN / 64, 2, 12), 256>>>(ga, 128);

    s2_node<<<NN / 8, 256>>>(h1, h2, h3, c1, c2, c3, del_t, dsc);
    s3_attn<<<NN / 8, 256>>>(nbr);

    GemmBatch gb;
    gb.p[0] = {pTP, Uiou_w, Uiou_b, pZp};
    gb.p[1] = {pTS, Uiou_w, Uiou_b, pZs};
    gb.p[2] = {pTE, Uiou_w, Uiou_b, pZe};
    for (int i = 3; i < 12; i++) gb.p[i] = gb.p[0];
    gemm_k<<<dim3(NN / 64, 6, 3), 256>>>(gb, 384);

    s5_final<<<NN / 4, 128>>>(iou1, iou2, iou3, out);
}

// round 7
// speedup vs baseline: 1.0296x; 1.0296x over previous
#include <cuda_runtime.h>
#include <cuda_bf16.h>
#include <math.h>
#include <stdint.h>

#define DEV __device__ __forceinline__

constexpr int   NN   = 8192;
constexpr int   HH   = 128;
constexpr float KPC  = -1.f;   // Poincare
constexpr float KSC  =  1.f;   // Sphere
constexpr float EPSV = 1e-6f;

// ======================= warp / vector helpers =======================
DEV float wsum(float v) {
#pragma unroll
    for (int o = 16; o; o >>= 1) v += __shfl_xor_sync(0xffffffffu, v, o);
    return v;
}
template <int V> DEV float vdot(const float* a, const float* b) {
    float s = 0.f;
#pragma unroll
    for (int t = 0; t < V; t++) s = fmaf(a[t], b[t], s);
    return wsum(s);
}
template <int V> DEV float vnorm2(const float* a) { return vdot<V>(a, a); }
DEV float safe_n(float n2) { return sqrtf(n2 + 1e-15f); }

DEV float tank(float u, float k) {
    if (k < 0.f) return tanhf(u);
    u = fminf(fmaxf(u, -1.47079f), 1.47079f);
    return tanf(u);
}
DEV float artank(float u, float k) {
    if (k < 0.f) {
        u = fminf(fmaxf(u, -1.f + 1e-5f), 1.f - 1e-5f);
        return atanhf(u);
    }
    return atanf(u);
}
DEV float sigf(float x) { return 1.f / (1.f + __expf(-x)); }
DEV float sdn(float d) { return (d >= 0.f) ? fmaxf(d, EPSV) : fminf(d, -EPSV); }

template <int V> DEV void projv(float* x, float k) {
    if (k < 0.f) {
        float n = safe_n(vnorm2<V>(x));
        float m = 1.f - 1e-4f;
        float s = (n > m) ? (m / n) : 1.f;
#pragma unroll
        for (int t = 0; t < V; t++) x[t] *= s;
    }
}
template <int V> DEV void expmap0v(float* o, const float* u, float k) {
    float n = safe_n(vnorm2<V>(u));
    float s = tank(n, k) / n;
#pragma unroll
    for (int t = 0; t < V; t++) o[t] = s * u[t];
    projv<V>(o, k);
}
template <int V> DEV void logmap0v(float* o, const float* y, float k) {
    float n = safe_n(vnorm2<V>(y));
    float s = artank(n, k) / n;
#pragma unroll
    for (int t = 0; t < V; t++) o[t] = s * y[t];
}
template <int V> DEV void maddv(float* o, const float* x, const float* y, float k) {
    float x2 = vnorm2<V>(x), y2 = vnorm2<V>(y), xy = vdot<V>(x, y);
    float A = 1.f - 2.f * k * xy - k * y2;
    float B = 1.f + k * x2;
    float den = 1.f - 2.f * k * xy + k * k * x2 * y2;
    float inv = 1.f / sdn(den);
#pragma unroll
    for (int t = 0; t < V; t++) o[t] = (A * x[t] + B * y[t]) * inv;
    projv<V>(o, k);
}
template <int V> DEV void pwmulv(float* o, const float* w, const float* x, float k) {
    float wx[V];
#pragma unroll
    for (int t = 0; t < V; t++) wx[t] = w[t] * x[t];
    float nx  = safe_n(vnorm2<V>(x));
    float nwx = safe_n(vnorm2<V>(wx));
    float s = tank(nwx / nx * artank(nx, k), k) / nwx;
#pragma unroll
    for (int t = 0; t < V; t++) o[t] = s * wx[t];
    projv<V>(o, k);
}
template <int V> DEV void pwscalv(float* o, const float* w, float g, float k) {
    float wx[V];
#pragma unroll
    for (int t = 0; t < V; t++) wx[t] = w[t] * g;
    float nx  = sqrtf(g * g + 1e-15f);
    float nwx = safe_n(vnorm2<V>(wx));
    float s = tank(nwx / nx * artank(nx, k), k) / nwx;
#pragma unroll
    for (int t = 0; t < V; t++) o[t] = s * wx[t];
    projv<V>(o, k);
}
template <int V> DEV void smulv(float* o, float r, const float* x, float k) {
    float n = safe_n(vnorm2<V>(x));
    float s = tank(r * artank(n, k), k) / n;
#pragma unroll
    for (int t = 0; t < V; t++) o[t] = s * x[t];
    projv<V>(o, k);
}
template <int V> DEV void wmid3v(float* o, const float* a, const float* b,
                                 const float* c, float k) {
    float la = 2.f / (1.f + k * vnorm2<V>(a));
    float lb = 2.f / (1.f + k * vnorm2<V>(b));
    float lc = 2.f / (1.f + k * vnorm2<V>(c));
    float den = fabsf(la + lb + lc - 3.f);
    float inv = 1.f / fmaxf(den, EPSV);
    float tmp[V];
#pragma unroll
    for (int t = 0; t < V; t++) tmp[t] = (la * a[t] + lb * b[t] + lc * c[t]) * inv;
    smulv<V>(o, 0.5f, tmp, k);
}

DEV void load4(float* v, const float* p, int lane) {
#pragma unroll
    for (int t = 0; t < 4; t++) v[t] = p[lane + 32 * t];
}
DEV void store4(float* p, const float* v, int lane) {
#pragma unroll
    for (int t = 0; t < 4; t++) p[lane + 32 * t] = v[t];
}
DEV void load12(float* v, const float* p, int lane) {
#pragma unroll
    for (int t = 0; t < 12; t++) v[t] = p[lane + 32 * t];
}

// dist(x,y,k) = 2*artan_k(||proj(mobius_add(-x,y,k))||).  p = dot(x,y).
DEV float distk(float x2, float y2, float p, float k) {
    float A = 1.f + 2.f * k * p - k * y2;     // coeff of (-x)
    float B = 1.f + k * x2;                   // coeff of y
    float den = 1.f + 2.f * k * p + k * k * x2 * y2;
    float nd = sdn(den);
    float q2 = fmaxf(A * A * x2 - 2.f * A * B * p + B * B * y2, 0.f) / (nd * nd);
    if (k < 0.f) {
        float n = sqrtf(q2 + 1e-15f);
        float m = 1.f - 1e-4f;
        if (n > m) { float s = m / n; q2 *= s * s; }
        float nf = sqrtf(q2 + 1e-15f);
        nf = fminf(nf, 1.f - 1e-5f);
        return 2.f * atanhf(nf);
    }
    float nf = sqrtf(q2 + 1e-15f);
    return 2.f * atanf(nf);
}

DEV void softmax8(const float* s, float* a) {
    float m = s[0];
#pragma unroll
    for (int q = 1; q < 8; q++) m = fmaxf(m, s[q]);
    float sum = 0.f;
#pragma unroll
    for (int q = 0; q < 8; q++) { a[q] = __expf(s[q] - m); sum += a[q]; }
    float inv = 1.f / sum;
#pragma unroll
    for (int q = 0; q < 8; q++) a[q] *= inv;
}

// ======================= device scratch =======================
__device__ float g_Lh1[NN * HH], g_Lh2[NN * HH], g_Lc1[NN * HH], g_Lc2[NN * HH];
__device__ float g_XPm[NN * HH], g_XSm[NN * HH];
__device__ float g_Yup1[NN * HH], g_Yup2[NN * HH], g_Yup3[NN * HH];
__device__ float g_Yc1[NN * HH],  g_Yc2[NN * HH],  g_Yc3[NN * HH];
__device__ float g_Yuf1[NN * HH], g_Yuf2[NN * HH], g_Yuf3[NN * HH];
__device__ float g_XQP[NN * HH],  g_XQS[NN * HH],  g_XQE[NN * HH];
__device__ float g_HP[NN * HH], g_HS[NN * HH], g_HE[NN * HH];
__device__ float g_CP[NN * HH], g_CS[NN * HH], g_CE[NN * HH];
__device__ float g_X1P[NN * HH], g_X1S[NN * HH];
__device__ float g_TP[NN * HH], g_TS[NN * HH], g_TE[NN * HH];
__device__ float g_C1[NN * HH], g_C2[NN * HH], g_C3[NN * HH];
__device__ float g_Zp[NN * 384], g_Zs[NN * 384], g_Ze[NN * 384];
__device__ float g_y2P[NN], g_y2S[NN], g_c2P[NN], g_c2S[NN], g_x2P[NN], g_x2S[NN];

// ======================= S0: logmap prep =======================
__global__ __launch_bounds__(256) void s0_prep(const float* __restrict__ x,
                                               const float* __restrict__ h1,
                                               const float* __restrict__ h2,
                                               const float* __restrict__ c1,
                                               const float* __restrict__ c2) {
    int n = (blockIdx.x * 256 + threadIdx.x) >> 5;
    if (n >= NN) return;
    int lane = threadIdx.x & 31;
    size_t off = (size_t)n * HH;
    float v[4], e[4], o[4];
    load4(v, x + off, lane);
    expmap0v<4>(e, v, KPC); logmap0v<4>(o, e, KPC); store4(g_XPm + off, o, lane);
    expmap0v<4>(e, v, KSC); logmap0v<4>(o, e, KSC); store4(g_XSm + off, o, lane);
    load4(v, h1 + off, lane); logmap0v<4>(o, v, KPC); store4(g_Lh1 + off, o, lane);
    load4(v, h2 + off, lane); logmap0v<4>(o, v, KSC); store4(g_Lh2 + off, o, lane);
    load4(v, c1 + off, lane); logmap0v<4>(o, v, KPC); store4(g_Lc1 + off, o, lane);
    load4(v, c2 + off, lane); logmap0v<4>(o, v, KSC); store4(g_Lc2 + off, o, lane);
}

// ======================= tensor-core GEMM: C = A @ W^T + b =======================
// A: [8192,128] rm, W: [NO,128] rm, C: [8192,NO]. TF32 mma with 3-term split.
// Block: 256 thr = 8 warps; tile M=128 x N=64; warp strip 16 x 64; K=128.
struct GemmDesc { const float* A; const float* W; const float* bias; float* C; };
struct GemmBatch { GemmDesc p[12]; };

DEV uint32_t f2tf(float x) {
    uint32_t r;
    asm("cvt.rna.tf32.f32 %0, %1;" : "=r"(r) : "f"(x));
    return r;
}

DEV void mma_tf32(float* d, const uint32_t* a, const uint32_t* b) {
    asm volatile(
        "mma.sync.aligned.m16n8k8.row.col.f32.tf32.tf32.f32 "
        "{%0,%1,%2,%3}, {%4,%5,%6,%7}, {%8,%9}, {%0,%1,%2,%3};"
        : "+f"(d[0]), "+f"(d[1]), "+f"(d[2]), "+f"(d[3])
        : "r"(a[0]), "r"(a[1]), "r"(a[2]), "r"(a[3]), "r"(b[0]), "r"(b[1]));
}

__global__ __launch_bounds__(256) void gemm_tc(GemmBatch gb, int NO) {
    GemmDesc d = gb.p[blockIdx.z];
    int warp = threadIdx.x >> 5, lane = threadIdx.x & 31;
    int g = lane >> 2, t = lane & 3;
    int m0 = blockIdx.x * 128 + warp * 16;
    int n0 = blockIdx.y * 64;

    float acc[8][4] = {};

    const float* Abase = d.A + (size_t)(m0 + g) * 128 + t;
    const float* Wbase = d.W + (size_t)(n0 + g) * 128 + t;

#pragma unroll 4
    for (int ks = 0; ks < 16; ks++) {
        int k0 = ks * 8;
        const float* Ap = Abase + k0;
        float a0 = __ldg(Ap), a1 = __ldg(Ap + 8 * 128);
        float a2 = __ldg(Ap + 4), a3 = __ldg(Ap + 8 * 128 + 4);
        uint32_t ahi[4] = {f2tf(a0), f2tf(a1), f2tf(a2), f2tf(a3)};
        uint32_t alo[4] = {
            f2tf(a0 - __uint_as_float(ahi[0])),
            f2tf(a1 - __uint_as_float(ahi[1])),
            f2tf(a2 - __uint_as_float(ahi[2])),
            f2tf(a3 - __uint_as_float(ahi[3]))};
#pragma unroll
        for (int nt = 0; nt < 8; nt++) {
            const float* Wp = Wbase + (size_t)nt * 8 * 128 + k0;
            float b0 = __ldg(Wp), b1 = __ldg(Wp + 4);
            uint32_t bhi[2] = {f2tf(b0), f2tf(b1)};
            uint32_t blo[2] = {
                f2tf(b0 - __uint_as_float(bhi[0])),
                f2tf(b1 - __uint_as_float(bhi[1]))};
            mma_tf32(acc[nt], ahi, bhi);
            mma_tf32(acc[nt], alo, bhi);
            mma_tf32(acc[nt], ahi, blo);
        }
    }

#pragma unroll
    for (int nt = 0; nt < 8; nt++) {
        int col = n0 + nt * 8 + 2 * t;
        float bi0 = d.bias[col], bi1 = d.bias[col + 1];
        size_t r0 = (size_t)(m0 + g) * NO;
        size_t r1 = (size_t)(m0 + g + 8) * NO;
        d.C[r0 + col]     = acc[nt][0] + bi0;
        d.C[r0 + col + 1] = acc[nt][1] + bi1;
        d.C[r1 + col]     = acc[nt][2] + bi0;
        d.C[r1 + col + 1] = acc[nt][3] + bi1;
    }
}

// ======================= S2: per-source-node stage =======================
__global__ __launch_bounds__(256) void s2_node(const float* __restrict__ h1,
                                               const float* __restrict__ h2,
                                               const float* __restrict__ h3,
                                               const float* __restrict__ c1,
                                               const float* __restrict__ c2,
                                               const float* __restrict__ c3,
                                               const float* __restrict__ del_t,
                                               const float* __restrict__ dscal) {
    int n = (blockIdx.x * 256 + threadIdx.x) >> 5;
    if (n >= NN) return;
    int lane = threadIdx.x & 31;
    size_t off = (size_t)n * HH;

    float mh1[4], mh2[4], mh3[4], lh1[4], lh2[4];
    load4(mh1, h1 + off, lane);
    load4(mh2, h2 + off, lane);
    load4(mh3, h3 + off, lane);
    load4(lh1, g_Lh1 + off, lane);
    load4(lh2, g_Lh2 + off, lane);

    float t[4], e[4], s1[4], s2v[4], s3v[4];
    load4(t, g_Yup1 + off, lane);
    expmap0v<4>(e, t, KPC);
#pragma unroll
    for (int i = 0; i < 4; i++) e[i] = sigf(e[i]);
    logmap0v<4>(s1, e, KPC);
    load4(t, g_Yup2 + off, lane);
    expmap0v<4>(e, t, KSC);
#pragma unroll
    for (int i = 0; i < 4; i++) e[i] = sigf(e[i]);
    logmap0v<4>(s2v, e, KSC);
    load4(t, g_Yup3 + off, lane);
#pragma unroll
    for (int i = 0; i < 4; i++) s3v[i] = sigf(t[i]);

    // ---- h_1p ----
    float ht1p[4], ht2p[4], ht3p[4], tmp[4], HP[4];
    pwmulv<4>(ht1p, s1, mh1, KPC);
    expmap0v<4>(tmp, lh2, KPC); pwmulv<4>(ht2p, s2v, tmp, KPC);
    expmap0v<4>(tmp, mh3, KPC); pwmulv<4>(ht3p, s3v, tmp, KPC);
    wmid3v<4>(HP, ht1p, ht2p, ht3p, KPC);
#pragma unroll
    for (int i = 0; i < 4; i++) HP[i] *= 3.f;
    store4(g_HP + off, HP, lane);
    float y2p = vnorm2<4>(HP);
    if (lane == 0) g_y2P[n] = y2p;

    // ---- h_1s ----
    float ht1s[4], ht2s[4], ht3s[4], HS[4];
    expmap0v<4>(tmp, lh1, KSC); pwmulv<4>(ht1s, s1, tmp, KPC);
    pwmulv<4>(ht2s, s2v, mh2, KSC);
    expmap0v<4>(tmp, mh3, KSC); pwmulv<4>(ht3s, s3v, tmp, KSC);
    wmid3v<4>(HS, ht1s, ht2s, ht3s, KPC);
#pragma unroll
    for (int i = 0; i < 4; i++) HS[i] *= 3.f;
    store4(g_HS + off, HS, lane);
    float y2s = vnorm2<4>(HS);
    if (lane == 0) g_y2S[n] = y2s;

    // ---- h_1e ----
    float he[4], l1[4], l2[4];
    logmap0v<4>(l1, ht1p, KPC);
    logmap0v<4>(l2, ht2s, KSC);
#pragma unroll
    for (int i = 0; i < 4; i++) he[i] = l1[i] + l2[i] + s3v[i] * mh3[i];
    store4(g_HE + off, he, lane);

    float g = dscal[0] / (del_t[n] + 1.f);

    // ---- Poincare cell ----
    {
        float mc[4]; load4(mc, c1 + off, lane);
        load4(t, g_Yc1 + off, lane);
        expmap0v<4>(e, t, KPC); logmap0v<4>(t, e, KPC);
#pragma unroll
        for (int i = 0; i < 4; i++) t[i] = tanhf(t[i]);
        float csk[4]; expmap0v<4>(csk, t, KPC);
        float pw[4]; pwscalv<4>(pw, csk, g, KPC);
        float neg[4];
#pragma unroll
        for (int i = 0; i < 4; i++) neg[i] = -csk[i];
        float m1[4]; maddv<4>(m1, neg, mc, KPC);
        float ckt[4]; maddv<4>(ckt, m1, pw, KPC);
        load4(t, g_Yuf1 + off, lane);
        expmap0v<4>(e, t, KPC); logmap0v<4>(t, e, KPC);
        float f[4];
#pragma unroll
        for (int i = 0; i < 4; i++) f[i] = sigf(t[i]);
        float CP[4]; pwmulv<4>(CP, f, ckt, KPC);
        store4(g_CP + off, CP, lane);
        float c2p = vnorm2<4>(CP);
        if (lane == 0) g_c2P[n] = c2p;
    }
    // ---- Sphere cell ----
    {
        float mc[4]; load4(mc, c2 + off, lane);
        load4(t, g_Yc2 + off, lane);
        expmap0v<4>(e, t, KSC); logmap0v<4>(t, e, KSC);
#pragma unroll
        for (int i = 0; i < 4; i++) t[i] = tanhf(t[i]);
        float csk[4]; expmap0v<4>(csk, t, KSC);
        float pw[4]; pwscalv<4>(pw, csk, g, KSC);
        float neg[4];
#pragma unroll
        for (int i = 0; i < 4; i++) neg[i] = -csk[i];
        float m1[4]; maddv<4>(m1, neg, mc, KSC);
        float ckt[4]; maddv<4>(ckt, m1, pw, KSC);
        load4(t, g_Yuf2 + off, lane);
        expmap0v<4>(e, t, KSC); logmap0v<4>(t, e, KSC);
        float f[4];
#pragma unroll
        for (int i = 0; i < 4; i++) f[i] = sigf(t[i]);
        float CS[4]; pwmulv<4>(CS, f, ckt, KSC);
        store4(g_CS + off, CS, lane);
        float c2s = vnorm2<4>(CS);
        if (lane == 0) g_c2S[n] = c2s;
    }
    // ---- Euclidean cell ----
    {
        float mc[4]; load4(mc, c3 + off, lane);
        load4(t, g_Yc3 + off, lane);
        float CE[4];
#pragma unroll
        for (int i = 0; i < 4; i++) {
            float csk = tanhf(t[i]);
            CE[i] = mc[i] - csk + csk * g;
        }
        load4(t, g_Yuf3 + off, lane);
#pragma unroll
        for (int i = 0; i < 4; i++) CE[i] *= sigf(t[i]);
        store4(g_CE + off, CE, lane);
    }
    // ---- dest-side queries ----
    {
        float q[4];
        load4(t, g_XQP + off, lane);
        expmap0v<4>(q, t, KPC);
        store4(g_X1P + off, q, lane);
        float x2 = vnorm2<4>(q);
        if (lane == 0) g_x2P[n] = x2;
        load4(t, g_XQS + off, lane);
        expmap0v<4>(q, t, KSC);
        store4(g_X1S + off, q, lane);
        x2 = vnorm2<4>(q);
        if (lane == 0) g_x2S[n] = x2;
    }
}

// ======================= S3: gather + attention + midpoints =======================
DEV void attn_hyp(size_t off, const int* jarr, const float* Xq, const float* x2t,
                  const float* Htab, const float* y2t, float kcur,
                  float* outT, int n, int lane) {
    float xq[4]; load4(xq, Xq + off, lane);
    float x2 = x2t[n];
    float vh[8][4], y2r[8], sc[8], a[8];
#pragma unroll
    for (int k = 0; k < 8; k++) {
        int j = jarr[k];
        load4(vh[k], Htab + (size_t)j * HH, lane);
        y2r[k] = y2t[j];
        float p = vdot<4>(xq, vh[k]);
        sc[k] = -distk(x2, y2r[k], p, kcur);
    }
    softmax8(sc, a);
    float num[4] = {0, 0, 0, 0};
    float ds = 0.f;
#pragma unroll
    for (int k = 0; k < 8; k++) {
        float lam = 2.f / (1.f + kcur * y2r[k]);
#pragma unroll
        for (int t = 0; t < 4; t++) num[t] = fmaf(a[k] * lam, vh[k][t], num[t]);
        ds += a[k] * (lam - 1.f);
    }
    float inv = 1.f / fmaxf(fabsf(ds), EPSV);
    float r[4];
#pragma unroll
    for (int t = 0; t < 4; t++) r[t] = num[t] * inv;
    float ht[4]; smulv<4>(ht, 0.5f, r, kcur);
    float lt[4]; logmap0v<4>(lt, ht, kcur);
    store4(outT + off, lt, lane);
}

DEV void cellmid(size_t off, const int* jarr, const float* Ctab, const float* c2t,
                 float kcur, float* outC, int lane) {
    float num[4] = {0, 0, 0, 0};
    float ds = 0.f;
#pragma unroll
    for (int k = 0; k < 8; k++) {
        int j = jarr[k];
        float cv[4]; load4(cv, Ctab + (size_t)j * HH, lane);
        float lam = 2.f / (1.f + kcur * c2t[j]);
#pragma unroll
        for (int t = 0; t < 4; t++) num[t] = fmaf(lam, cv[t], num[t]);
        ds += lam - 1.f;
    }
    float inv = 1.f / fmaxf(fabsf(ds), EPSV);
    float r[4];
#pragma unroll
    for (int t = 0; t < 4; t++) r[t] = num[t] * inv;
    float o[4]; smulv<4>(o, 0.5f, r, kcur);
    store4(outC + off, o, lane);
}

__global__ __launch_bounds__(256) void s3_attn(const int* __restrict__ nbr) {
    int n = (blockIdx.x * 256 + threadIdx.x) >> 5;
    if (n >= NN) return;
    int lane = threadIdx.x & 31;
    size_t off = (size_t)n * HH;
    int jarr[8];
#pragma unroll
    for (int k = 0; k < 8; k++) jarr[k] = nbr[n * 8 + k];

    attn_hyp(off, jarr, g_X1P, g_x2P, g_HP, g_y2P, KPC, g_TP, n, lane);
    attn_hyp(off, jarr, g_X1S, g_x2S, g_HS, g_y2S, KSC, g_TS, n, lane);

    // Euclidean attention
    {
        float xq[4]; load4(xq, g_XQE + off, lane);
        float vh[8][4], sc[8], a[8];
#pragma unroll
        for (int k = 0; k < 8; k++) {
            load4(vh[k], g_HE + (size_t)jarr[k] * HH, lane);
            sc[k] = vdot<4>(xq, vh[k]) * 0.08838834764831845f;  // 1/sqrt(128)
        }
        softmax8(sc, a);
        float he[4] = {0, 0, 0, 0};
#pragma unroll
        for (int k = 0; k < 8; k++)
#pragma unroll
            for (int t = 0; t < 4; t++) he[t] = fmaf(a[k], vh[k][t], he[t]);
        store4(g_TE + off, he, lane);
    }

    cellmid(off, jarr, g_CP, g_c2P, KPC, g_C1, lane);
    cellmid(off, jarr, g_CS, g_c2S, KSC, g_C2, lane);

    // c_3 = sum_k CE(j)
    {
        float s[4] = {0, 0, 0, 0};
#pragma unroll
        for (int k = 0; k < 8; k++) {
            float cv[4]; load4(cv, g_CE + (size_t)jarr[k] * HH, lane);
#pragma unroll
            for (int t = 0; t < 4; t++) s[t] += cv[t];
        }
        store4(g_C3 + off, s, lane);
    }
}

// ======================= S5: final node update =======================
__global__ __launch_bounds__(128) void s5_final(const float* __restrict__ iou1,
                                                const float* __restrict__ iou2,
                                                const float* __restrict__ iou3,
                                                float* __restrict__ out) {
    int n = (blockIdx.x * 128 + threadIdx.x) >> 5;
    if (n >= NN) return;
    int lane = threadIdx.x & 31;
    size_t o384 = (size_t)n * 384, o128 = (size_t)n * HH;
    const size_t SL = (size_t)NN * HH;

    // ---- Poincare ----
    {
        float z[12], e[12], io[12], ni[12];
        load12(z, g_Zp + o384, lane);
        expmap0v<12>(e, z, KPC);
        load12(io, iou1 + o384, lane);
        maddv<12>(ni, io, e, KPC);
        float ip[4], op[4], up[4];
        logmap0v<4>(ip, ni + 0, KPC);
        logmap0v<4>(op, ni + 4, KPC);
        logmap0v<4>(up, ni + 8, KPC);
#pragma unroll
        for (int i = 0; i < 4; i++) { ip[i] = sigf(ip[i]); op[i] = sigf(op[i]); up[i] = tanhf(up[i]); }
        float pu[4]; pwmulv<4>(pu, ip, up, KPC);
        float cv[4]; load4(cv, g_C1 + o128, lane);
        float nc[4]; maddv<4>(nc, pu, cv, KPC);
        float lg[4]; logmap0v<4>(lg, nc, KPC);
#pragma unroll
        for (int i = 0; i < 4; i++) lg[i] = tanhf(lg[i]);
        float nh[4]; pwmulv<4>(nh, op, lg, KPC);
        store4(out + 0 * SL + o128, nh, lane);
        store4(out + 1 * SL + o128, nc, lane);
    }
    // ---- Sphere ----
    {
        float z[12], e[12], io[12], ni[12];
        load12(z, g_Zs + o384, lane);
        expmap0v<12>(e, z, KSC);
        load12(io, iou2 + o384, lane);
        maddv<12>(ni, io, e, KSC);
        float ip[4], op[4], up[4];
        logmap0v<4>(ip, ni + 0, KSC);
        logmap0v<4>(op, ni + 4, KSC);
        logmap0v<4>(up, ni + 8, KSC);
#pragma unroll
        for (int i = 0; i < 4; i++) { ip[i] = sigf(ip[i]); op[i] = sigf(op[i]); up[i] = tanhf(up[i]); }
        float pu[4]; pwmulv<4>(pu, ip, up, KSC);
        float cv[4]; load4(cv, g_C2 + o128, lane);
        float nc[4]; maddv<4>(nc, pu, cv, KSC);
        float lg[4]; logmap0v<4>(lg, nc, KSC);
#pragma unroll
        for (int i = 0; i < 4; i++) lg[i] = tanhf(lg[i]);
        float nh[4]; pwmulv<4>(nh, op, lg, KSC);
        store4(out + 2 * SL + o128, nh, lane);
        store4(out + 3 * SL + o128, nc, lane);
    }
    // ---- Euclidean ----
    {
        float z[12], io[12];
        load12(z, g_Ze + o384, lane);
        load12(io, iou3 + o384, lane);
        float cv[4]; load4(cv, g_C3 + o128, lane);
        float nc[4], nh[4];
#pragma unroll
        for (int i = 0; i < 4; i++) {
            float ie = sigf(io[i] + z[i]);
            float oe = sigf(io[i + 4] + z[i + 4]);
            float ue = tanhf(io[i + 8] + z[i + 8]);
            nc[i] = ie * ue + cv[i];
            nh[i] = oe * tanhf(nc[i]);
        }
        store4(out + 4 * SL + o128, nh, lane);
        store4(out + 5 * SL + o128, nc, lane);
    }
}

// ======================= launch =======================
extern "C" void kernel_launch(void* const* d_in, const int* in_sizes, int n_in,
                              void* d_out, int out_size) {
    const float* x     = (const float*)d_in[0];
    const float* h1    = (const float*)d_in[1];
    const float* c1    = (const float*)d_in[2];
    const float* h2    = (const float*)d_in[3];
    const float* c2    = (const float*)d_in[4];
    const float* h3    = (const float*)d_in[5];
    const float* c3    = (const float*)d_in[6];
    const float* del_t = (const float*)d_in[7];
    const float* iou1  = (const float*)d_in[8];
    const float* iou2  = (const float*)d_in[9];
    const float* iou3  = (const float*)d_in[10];
    const float* Wq_w  = (const float*)d_in[11];
    const float* Wq_b  = (const float*)d_in[12];
    const float* Wc_w  = (const float*)d_in[13];
    const float* Wc_b  = (const float*)d_in[14];
    const float* Uf_w  = (const float*)d_in[15];
    const float* Uf_b  = (const float*)d_in[16];
    const float* Up_w  = (const float*)d_in[17];
    const float* Up_b  = (const float*)d_in[18];
    const float* Uiou_w = (const float*)d_in[19];
    const float* Uiou_b = (const float*)d_in[20];
    const float* dsc   = (const float*)d_in[21];
    const int*   nbr   = (const int*)d_in[22];
    float* out = (float*)d_out;

    float *pLh1, *pLh2, *pLc1, *pLc2, *pXPm, *pXSm;
    float *pYup1, *pYup2, *pYup3, *pYc1, *pYc2, *pYc3, *pYuf1, *pYuf2, *pYuf3;
    float *pXQP, *pXQS, *pXQE, *pTP, *pTS, *pTE, *pZp, *pZs, *pZe;
    cudaGetSymbolAddress((void**)&pLh1, g_Lh1);
    cudaGetSymbolAddress((void**)&pLh2, g_Lh2);
    cudaGetSymbolAddress((void**)&pLc1, g_Lc1);
    cudaGetSymbolAddress((void**)&pLc2, g_Lc2);
    cudaGetSymbolAddress((void**)&pXPm, g_XPm);
    cudaGetSymbolAddress((void**)&pXSm, g_XSm);
    cudaGetSymbolAddress((void**)&pYup1, g_Yup1);
    cudaGetSymbolAddress((void**)&pYup2, g_Yup2);
    cudaGetSymbolAddress((void**)&pYup3, g_Yup3);
    cudaGetSymbolAddress((void**)&pYc1, g_Yc1);
    cudaGetSymbolAddress((void**)&pYc2, g_Yc2);
    cudaGetSymbolAddress((void**)&pYc3, g_Yc3);
    cudaGetSymbolAddress((void**)&pYuf1, g_Yuf1);
    cudaGetSymbolAddress((void**)&pYuf2, g_Yuf2);
    cudaGetSymbolAddress((void**)&pYuf3, g_Yuf3);
    cudaGetSymbolAddress((void**)&pXQP, g_XQP);
    cudaGetSymbolAddress((void**)&pXQS, g_XQS);
    cudaGetSymbolAddress((void**)&pXQE, g_XQE);
    cudaGetSymbolAddress((void**)&pTP, g_TP);
    cudaGetSymbolAddress((void**)&pTS, g_TS);
    cudaGetSymbolAddress((void**)&pTE, g_TE);
    cudaGetSymbolAddress((void**)&pZp, g_Zp);
    cudaGetSymbolAddress((void**)&pZs, g_Zs);
    cudaGetSymbolAddress((void**)&pZe, g_Ze);

    s0_prep<<<NN / 8, 256>>>(x, h1, h2, c1, c2);

    GemmBatch ga;
    ga.p[0]  = {pLh1, Up_w, Up_b, pYup1};
    ga.p[1]  = {pLh2, Up_w, Up_b, pYup2};
    ga.p[2]  = {h3,   Up_w, Up_b, pYup3};
    ga.p[3]  = {pLc1, Wc_w, Wc_b, pYc1};
    ga.p[4]  = {pLc2, Wc_w, Wc_b, pYc2};
    ga.p[5]  = {c3,   Wc_w, Wc_b, pYc3};
    ga.p[6]  = {pLh1, Uf_w, Uf_b, pYuf1};
    ga.p[7]  = {pLh2, Uf_w, Uf_b, pYuf2};
    ga.p[8]  = {h3,   Uf_w, Uf_b, pYuf3};
    ga.p[9]  = {pXPm, Wq_w, Wq_b, pXQP};
    ga.p[10] = {pXSm, Wq_w, Wq_b, pXQS};
    ga.p[11] = {x,    Wq_w, Wq_b, pXQE};
    gemm_tc<<<dim3(NN / 128, 2, 12), 256>>>(ga, 128);

    s2_node<<<NN / 8, 256>>>(h1, h2, h3, c1, c2, c3, del_t, dsc);
    s3_attn<<<NN / 8, 256>>>(nbr);

    GemmBatch gb;
    gb.p[0] = {pTP, Uiou_w, Uiou_b, pZp};
    gb.p[1] = {pTS, Uiou_w, Uiou_b, pZs};
    gb.p[2] = {pTE, Uiou_w, Uiou_b, pZe};
    for (int i = 3; i < 12; i++) gb.p[i] = gb.p[0];
    gemm_tc<<<dim3(NN / 128, 6, 3), 256>>>(gb, 384);

    s5_final<<<NN / 4, 128>>>(iou1, iou2, iou3, out);
}

// round 8
// speedup vs baseline: 1.6378x; 1.5907x over previous
#include <cuda_runtime.h>
#include <cuda_bf16.h>
#include <math.h>
#include <stdint.h>

#define DEV __device__ __forceinline__

constexpr int   NN   = 8192;
constexpr int   HH   = 128;
constexpr float KPC  = -1.f;   // Poincare
constexpr float KSC  =  1.f;   // Sphere
constexpr float EPSV = 1e-6f;

// ======================= fast transcendentals =======================
DEV float tanh_f(float x) {
    float ax = fabsf(x);
    float t = __expf(-2.f * ax);
    float r = (1.f - t) / (1.f + t);
    return copysignf(r, x);
}
DEV float atanh_f(float x) {  // caller guarantees |x| <= 1-1e-5
    return 0.5f * __logf((1.f + x) / (1.f - x));
}

// ======================= warp / vector helpers =======================
DEV float wsum(float v) {
#pragma unroll
    for (int o = 16; o; o >>= 1) v += __shfl_xor_sync(0xffffffffu, v, o);
    return v;
}
template <int V> DEV float vdot(const float* a, const float* b) {
    float s = 0.f;
#pragma unroll
    for (int t = 0; t < V; t++) s = fmaf(a[t], b[t], s);
    return wsum(s);
}
template <int V> DEV float vnorm2(const float* a) { return vdot<V>(a, a); }
DEV float safe_n(float n2) { return sqrtf(n2 + 1e-15f); }

DEV float tank(float u, float k) {
    if (k < 0.f) return tanh_f(u);
    u = fminf(fmaxf(u, -1.47079f), 1.47079f);
    return __tanf(u);
}
DEV float artank(float u, float k) {
    if (k < 0.f) {
        u = fminf(fmaxf(u, -1.f + 1e-5f), 1.f - 1e-5f);
        return atanh_f(u);
    }
    return atanf(u);
}
DEV float sigf(float x) { return 1.f / (1.f + __expf(-x)); }
DEV float sdn(float d) { return (d >= 0.f) ? fmaxf(d, EPSV) : fminf(d, -EPSV); }

template <int V> DEV void projv(float* x, float k) {
    if (k < 0.f) {
        float n = safe_n(vnorm2<V>(x));
        float m = 1.f - 1e-4f;
        float s = (n > m) ? (m / n) : 1.f;
#pragma unroll
        for (int t = 0; t < V; t++) x[t] *= s;
    }
}
template <int V> DEV void expmap0v(float* o, const float* u, float k) {
    float n = safe_n(vnorm2<V>(u));
    float s = tank(n, k) / n;
#pragma unroll
    for (int t = 0; t < V; t++) o[t] = s * u[t];
    projv<V>(o, k);
}
template <int V> DEV void logmap0v(float* o, const float* y, float k) {
    float n = safe_n(vnorm2<V>(y));
    float s = artank(n, k) / n;
#pragma unroll
    for (int t = 0; t < V; t++) o[t] = s * y[t];
}
template <int V> DEV void maddv(float* o, const float* x, const float* y, float k) {
    float x2 = vnorm2<V>(x), y2 = vnorm2<V>(y), xy = vdot<V>(x, y);
    float A = 1.f - 2.f * k * xy - k * y2;
    float B = 1.f + k * x2;
    float den = 1.f - 2.f * k * xy + k * k * x2 * y2;
    float inv = 1.f / sdn(den);
#pragma unroll
    for (int t = 0; t < V; t++) o[t] = (A * x[t] + B * y[t]) * inv;
    projv<V>(o, k);
}
template <int V> DEV void pwmulv(float* o, const float* w, const float* x, float k) {
    float wx[V];
#pragma unroll
    for (int t = 0; t < V; t++) wx[t] = w[t] * x[t];
    float nx  = safe_n(vnorm2<V>(x));
    float nwx = safe_n(vnorm2<V>(wx));
    float s = tank(nwx / nx * artank(nx, k), k) / nwx;
#pragma unroll
    for (int t = 0; t < V; t++) o[t] = s * wx[t];
    projv<V>(o, k);
}
template <int V> DEV void pwscalv(float* o, const float* w, float g, float k) {
    float wx[V];
#pragma unroll
    for (int t = 0; t < V; t++) wx[t] = w[t] * g;
    float nx  = sqrtf(g * g + 1e-15f);
    float nwx = safe_n(vnorm2<V>(wx));
    float s = tank(nwx / nx * artank(nx, k), k) / nwx;
#pragma unroll
    for (int t = 0; t < V; t++) o[t] = s * wx[t];
    projv<V>(o, k);
}
template <int V> DEV void smulv(float* o, float r, const float* x, float k) {
    float n = safe_n(vnorm2<V>(x));
    float s = tank(r * artank(n, k), k) / n;
#pragma unroll
    for (int t = 0; t < V; t++) o[t] = s * x[t];
    projv<V>(o, k);
}
template <int V> DEV void wmid3v(float* o, const float* a, const float* b,
                                 const float* c, float k) {
    float la = 2.f / (1.f + k * vnorm2<V>(a));
    float lb = 2.f / (1.f + k * vnorm2<V>(b));
    float lc = 2.f / (1.f + k * vnorm2<V>(c));
    float den = fabsf(la + lb + lc - 3.f);
    float inv = 1.f / fmaxf(den, EPSV);
    float tmp[V];
#pragma unroll
    for (int t = 0; t < V; t++) tmp[t] = (la * a[t] + lb * b[t] + lc * c[t]) * inv;
    smulv<V>(o, 0.5f, tmp, k);
}

DEV void load4(float* v, const float* p, int lane) {
#pragma unroll
    for (int t = 0; t < 4; t++) v[t] = p[lane + 32 * t];
}
DEV void store4(float* p, const float* v, int lane) {
#pragma unroll
    for (int t = 0; t < 4; t++) p[lane + 32 * t] = v[t];
}
DEV void load12(float* v, const float* p, int lane) {
#pragma unroll
    for (int t = 0; t < 12; t++) v[t] = p[lane + 32 * t];
}
DEV void store4bf(__nv_bfloat16* hp, __nv_bfloat16* lp, const float* v, int lane) {
#pragma unroll
    for (int t = 0; t < 4; t++) {
        float x = v[t];
        __nv_bfloat16 h = __float2bfloat16(x);
        hp[lane + 32 * t] = h;
        lp[lane + 32 * t] = __float2bfloat16(x - __bfloat162float(h));
    }
}

// dist(x,y,k) = 2*artan_k(||proj(mobius_add(-x,y,k))||).  p = dot(x,y).
DEV float distk(float x2, float y2, float p, float k) {
    float A = 1.f + 2.f * k * p - k * y2;     // coeff of (-x)
    float B = 1.f + k * x2;                   // coeff of y
    float den = 1.f + 2.f * k * p + k * k * x2 * y2;
    float nd = sdn(den);
    float q2 = fmaxf(A * A * x2 - 2.f * A * B * p + B * B * y2, 0.f) / (nd * nd);
    if (k < 0.f) {
        float n = sqrtf(q2 + 1e-15f);
        float m = 1.f - 1e-4f;
        if (n > m) { float s = m / n; q2 *= s * s; }
        float nf = sqrtf(q2 + 1e-15f);
        nf = fminf(nf, 1.f - 1e-5f);
        return 2.f * atanh_f(nf);
    }
    float nf = sqrtf(q2 + 1e-15f);
    return 2.f * atanf(nf);
}

DEV void softmax8(const float* s, float* a) {
    float m = s[0];
#pragma unroll
    for (int q = 1; q < 8; q++) m = fmaxf(m, s[q]);
    float sum = 0.f;
#pragma unroll
    for (int q = 0; q < 8; q++) { a[q] = __expf(s[q] - m); sum += a[q]; }
    float inv = 1.f / sum;
#pragma unroll
    for (int q = 0; q < 8; q++) a[q] *= inv;
}

// ======================= device scratch =======================
// float scratch
__device__ float g_Lh1[NN * HH], g_Lh2[NN * HH];
__device__ float g_Yup1[NN * HH], g_Yup2[NN * HH], g_Yup3[NN * HH];
__device__ float g_Yc1[NN * HH],  g_Yc2[NN * HH],  g_Yc3[NN * HH];
__device__ float g_Yuf1[NN * HH], g_Yuf2[NN * HH], g_Yuf3[NN * HH];
__device__ float g_XQP[NN * HH],  g_XQS[NN * HH],  g_XQE[NN * HH];
__device__ float g_HP[NN * HH], g_HS[NN * HH], g_HE[NN * HH];
__device__ float g_CP[NN * HH], g_CS[NN * HH], g_CE[NN * HH];
__device__ float g_X1P[NN * HH], g_X1S[NN * HH];
__device__ float g_C1[NN * HH], g_C2[NN * HH], g_C3[NN * HH];
__device__ float g_Zp[NN * 384], g_Zs[NN * 384], g_Ze[NN * 384];
__device__ float g_y2P[NN], g_y2S[NN], g_c2P[NN], g_c2S[NN], g_x2P[NN], g_x2S[NN];

// bf16 hi/lo GEMM inputs
__device__ __nv_bfloat16 b_Lh1h[NN*HH], b_Lh1l[NN*HH], b_Lh2h[NN*HH], b_Lh2l[NN*HH];
__device__ __nv_bfloat16 b_Lc1h[NN*HH], b_Lc1l[NN*HH], b_Lc2h[NN*HH], b_Lc2l[NN*HH];
__device__ __nv_bfloat16 b_XPh[NN*HH],  b_XPl[NN*HH],  b_XSh[NN*HH],  b_XSl[NN*HH];
__device__ __nv_bfloat16 b_xh[NN*HH],   b_xl[NN*HH];
__device__ __nv_bfloat16 b_h3h[NN*HH],  b_h3l[NN*HH],  b_c3h[NN*HH],  b_c3l[NN*HH];
__device__ __nv_bfloat16 b_TPh[NN*HH],  b_TPl[NN*HH],  b_TSh[NN*HH],  b_TSl[NN*HH];
__device__ __nv_bfloat16 b_TEh[NN*HH],  b_TEl[NN*HH];
__device__ __nv_bfloat16 b_Wqh[128*128], b_Wql[128*128], b_Wch[128*128], b_Wcl[128*128];
__device__ __nv_bfloat16 b_Ufh[128*128], b_Ufl[128*128], b_Uph[128*128], b_Upl[128*128];
__device__ __nv_bfloat16 b_Uih[384*128], b_Uil[384*128];

// ======================= cvt pass: fp32 -> bf16 hi/lo =======================
struct CvtJob { const float* s; __nv_bfloat16* h; __nv_bfloat16* l; int n; };
struct CvtBatch { CvtJob j[8]; };

__global__ __launch_bounds__(256) void cvtk(CvtBatch cb) {
    CvtJob jb = cb.j[blockIdx.y];
    int i = (blockIdx.x * 256 + threadIdx.x) * 4;
    if (i >= jb.n) return;
    float4 v = *(const float4*)(jb.s + i);
    float vv[4] = {v.x, v.y, v.z, v.w};
#pragma unroll
    for (int t = 0; t < 4; t++) {
        __nv_bfloat16 h = __float2bfloat16(vv[t]);
        jb.h[i + t] = h;
        jb.l[i + t] = __float2bfloat16(vv[t] - __bfloat162float(h));
    }
}

// ======================= S0: logmap prep =======================
__global__ __launch_bounds__(256) void s0_prep(const float* __restrict__ x,
                                               const float* __restrict__ h1,
                                               const float* __restrict__ h2,
                                               const float* __restrict__ c1,
                                               const float* __restrict__ c2) {
    int n = (blockIdx.x * 256 + threadIdx.x) >> 5;
    if (n >= NN) return;
    int lane = threadIdx.x & 31;
    size_t off = (size_t)n * HH;
    float v[4], e[4], o[4];
    load4(v, x + off, lane);
    expmap0v<4>(e, v, KPC); logmap0v<4>(o, e, KPC); store4bf(b_XPh + off, b_XPl + off, o, lane);
    expmap0v<4>(e, v, KSC); logmap0v<4>(o, e, KSC); store4bf(b_XSh + off, b_XSl + off, o, lane);
    load4(v, h1 + off, lane); logmap0v<4>(o, v, KPC);
    store4(g_Lh1 + off, o, lane); store4bf(b_Lh1h + off, b_Lh1l + off, o, lane);
    load4(v, h2 + off, lane); logmap0v<4>(o, v, KSC);
    store4(g_Lh2 + off, o, lane); store4bf(b_Lh2h + off, b_Lh2l + off, o, lane);
    load4(v, c1 + off, lane); logmap0v<4>(o, v, KPC); store4bf(b_Lc1h + off, b_Lc1l + off, o, lane);
    load4(v, c2 + off, lane); logmap0v<4>(o, v, KSC); store4bf(b_Lc2h + off, b_Lc2l + off, o, lane);
}

// ======================= bf16 split tensor-core GEMM =======================
// C[8192,NO] = A[8192,128] @ W[NO,128]^T + b  via 3-term bf16 split mma.
// Block 256 thr = 8 warps, tile M=128 x N=64, full K=128 staged in smem.
struct GemmDesc {
    const __nv_bfloat16 *Ah, *Al, *Wh, *Wl;
    const float* bias; float* C;
};
struct GemmBatch { GemmDesc p[12]; };

constexpr int RS = 136;          // smem row stride in bf16 (272B, conflict-free)
constexpr int SM_AH = 0;
constexpr int SM_AL = 128 * RS;
constexpr int SM_WH = 2 * 128 * RS;
constexpr int SM_WL = 2 * 128 * RS + 64 * RS;
constexpr int SMEM_ELEMS = 2 * 128 * RS + 2 * 64 * RS;   // 52224 bf16
constexpr int SMEM_BYTES = SMEM_ELEMS * 2;               // 104448 B

DEV uint32_t lds32(const __nv_bfloat16* p) { return *(const uint32_t*)p; }

DEV void mma_bf(float* d, const uint32_t* a, const uint32_t* b) {
    asm volatile(
        "mma.sync.aligned.m16n8k16.row.col.f32.bf16.bf16.f32 "
        "{%0,%1,%2,%3}, {%4,%5,%6,%7}, {%8,%9}, {%0,%1,%2,%3};"
        : "+f"(d[0]), "+f"(d[1]), "+f"(d[2]), "+f"(d[3])
        : "r"(a[0]), "r"(a[1]), "r"(a[2]), "r"(a[3]), "r"(b[0]), "r"(b[1]));
}

__global__ __launch_bounds__(256) void gemm_bf(GemmBatch gb, int NO) {
    extern __shared__ __align__(16) __nv_bfloat16 sm[];
    GemmDesc d = gb.p[blockIdx.z];
    int tid = threadIdx.x;
    int warp = tid >> 5, lane = tid & 31;
    int g = lane >> 2, t = lane & 3;
    int m0 = blockIdx.x * 128, n0 = blockIdx.y * 64;

    // cooperative stage: A (128x128) hi+lo, W (64x128) hi+lo, 16B chunks
#pragma unroll
    for (int it = 0; it < 8; it++) {
        int idx = tid + it * 256;            // 2048 chunks
        int r = idx >> 4, c = idx & 15;
        *(uint4*)(sm + SM_AH + r * RS + c * 8) =
            *(const uint4*)(d.Ah + (size_t)(m0 + r) * 128 + c * 8);
        *(uint4*)(sm + SM_AL + r * RS + c * 8) =
            *(const uint4*)(d.Al + (size_t)(m0 + r) * 128 + c * 8);
    }
#pragma unroll
    for (int it = 0; it < 4; it++) {
        int idx = tid + it * 256;            // 1024 chunks
        int r = idx >> 4, c = idx & 15;
        *(uint4*)(sm + SM_WH + r * RS + c * 8) =
            *(const uint4*)(d.Wh + (size_t)(n0 + r) * 128 + c * 8);
        *(uint4*)(sm + SM_WL + r * RS + c * 8) =
            *(const uint4*)(d.Wl + (size_t)(n0 + r) * 128 + c * 8);
    }
    __syncthreads();

    float acc[8][4] = {};
    int rowA = warp * 16 + g;
    const __nv_bfloat16* pa0h = sm + SM_AH + rowA * RS + 2 * t;
    const __nv_bfloat16* pa0l = sm + SM_AL + rowA * RS + 2 * t;

#pragma unroll
    for (int ks = 0; ks < 8; ks++) {
        int kb = ks * 16;
        uint32_t ah[4] = { lds32(pa0h + kb),            lds32(pa0h + 8 * RS + kb),
                           lds32(pa0h + kb + 8),        lds32(pa0h + 8 * RS + kb + 8) };
        uint32_t al[4] = { lds32(pa0l + kb),            lds32(pa0l + 8 * RS + kb),
                           lds32(pa0l + kb + 8),        lds32(pa0l + 8 * RS + kb + 8) };
#pragma unroll
        for (int nt = 0; nt < 8; nt++) {
            const __nv_bfloat16* pwh = sm + SM_WH + (nt * 8 + g) * RS + 2 * t + kb;
            const __nv_bfloat16* pwl = sm + SM_WL + (nt * 8 + g) * RS + 2 * t + kb;
            uint32_t bh[2] = { lds32(pwh), lds32(pwh + 8) };
            uint32_t bl[2] = { lds32(pwl), lds32(pwl + 8) };
            mma_bf(acc[nt], ah, bh);
            mma_bf(acc[nt], al, bh);
            mma_bf(acc[nt], ah, bl);
        }
    }

#pragma unroll
    for (int nt = 0; nt < 8; nt++) {
        int col = n0 + nt * 8 + 2 * t;
        float bi0 = d.bias[col], bi1 = d.bias[col + 1];
        size_t r0 = (size_t)(m0 + warp * 16 + g) * NO;
        size_t r1 = (size_t)(m0 + warp * 16 + g + 8) * NO;
        d.C[r0 + col]     = acc[nt][0] + bi0;
        d.C[r0 + col + 1] = acc[nt][1] + bi1;
        d.C[r1 + col]     = acc[nt][2] + bi0;
        d.C[r1 + col + 1] = acc[nt][3] + bi1;
    }
}

// ======================= S2: per-source-node stage =======================
__global__ __launch_bounds__(256) void s2_node(const float* __restrict__ h1,
                                               const float* __restrict__ h2,
                                               const float* __restrict__ h3,
                                               const float* __restrict__ c1,
                                               const float* __restrict__ c2,
                                               const float* __restrict__ c3,
                                               const float* __restrict__ del_t,
                                               const float* __restrict__ dscal) {
    int n = (blockIdx.x * 256 + threadIdx.x) >> 5;
    if (n >= NN) return;
    int lane = threadIdx.x & 31;
    size_t off = (size_t)n * HH;

    float mh1[4], mh2[4], mh3[4], lh1[4], lh2[4];
    load4(mh1, h1 + off, lane);
    load4(mh2, h2 + off, lane);
    load4(mh3, h3 + off, lane);
    load4(lh1, g_Lh1 + off, lane);
    load4(lh2, g_Lh2 + off, lane);

    float t[4], e[4], s1[4], s2v[4], s3v[4];
    load4(t, g_Yup1 + off, lane);
    expmap0v<4>(e, t, KPC);
#pragma unroll
    for (int i = 0; i < 4; i++) e[i] = sigf(e[i]);
    logmap0v<4>(s1, e, KPC);
    load4(t, g_Yup2 + off, lane);
    expmap0v<4>(e, t, KSC);
#pragma unroll
    for (int i = 0; i < 4; i++) e[i] = sigf(e[i]);
    logmap0v<4>(s2v, e, KSC);
    load4(t, g_Yup3 + off, lane);
#pragma unroll
    for (int i = 0; i < 4; i++) s3v[i] = sigf(t[i]);

    // ---- h_1p ----
    float ht1p[4], ht2p[4], ht3p[4], tmp[4], HP[4];
    pwmulv<4>(ht1p, s1, mh1, KPC);
    expmap0v<4>(tmp, lh2, KPC); pwmulv<4>(ht2p, s2v, tmp, KPC);
    expmap0v<4>(tmp, mh3, KPC); pwmulv<4>(ht3p, s3v, tmp, KPC);
    wmid3v<4>(HP, ht1p, ht2p, ht3p, KPC);
#pragma unroll
    for (int i = 0; i < 4; i++) HP[i] *= 3.f;
    store4(g_HP + off, HP, lane);
    float y2p = vnorm2<4>(HP);
    if (lane == 0) g_y2P[n] = y2p;

    // ---- h_1s ----
    float ht1s[4], ht2s[4], ht3s[4], HS[4];
    expmap0v<4>(tmp, lh1, KSC); pwmulv<4>(ht1s, s1, tmp, KPC);
    pwmulv<4>(ht2s, s2v, mh2, KSC);
    expmap0v<4>(tmp, mh3, KSC); pwmulv<4>(ht3s, s3v, tmp, KSC);
    wmid3v<4>(HS, ht1s, ht2s, ht3s, KPC);
#pragma unroll
    for (int i = 0; i < 4; i++) HS[i] *= 3.f;
    store4(g_HS + off, HS, lane);
    float y2s = vnorm2<4>(HS);
    if (lane == 0) g_y2S[n] = y2s;

    // ---- h_1e ----
    float he[4], l1[4], l2[4];
    logmap0v<4>(l1, ht1p, KPC);
    logmap0v<4>(l2, ht2s, KSC);
#pragma unroll
    for (int i = 0; i < 4; i++) he[i] = l1[i] + l2[i] + s3v[i] * mh3[i];
    store4(g_HE + off, he, lane);

    float g = dscal[0] / (del_t[n] + 1.f);

    // ---- Poincare cell ----
    {
        float mc[4]; load4(mc, c1 + off, lane);
        load4(t, g_Yc1 + off, lane);
        expmap0v<4>(e, t, KPC); logmap0v<4>(t, e, KPC);
#pragma unroll
        for (int i = 0; i < 4; i++) t[i] = tanh_f(t[i]);
        float csk[4]; expmap0v<4>(csk, t, KPC);
        float pw[4]; pwscalv<4>(pw, csk, g, KPC);
        float neg[4];
#pragma unroll
        for (int i = 0; i < 4; i++) neg[i] = -csk[i];
        float m1[4]; maddv<4>(m1, neg, mc, KPC);
        float ckt[4]; maddv<4>(ckt, m1, pw, KPC);
        load4(t, g_Yuf1 + off, lane);
        expmap0v<4>(e, t, KPC); logmap0v<4>(t, e, KPC);
        float f[4];
#pragma unroll
        for (int i = 0; i < 4; i++) f[i] = sigf(t[i]);
        float CP[4]; pwmulv<4>(CP, f, ckt, KPC);
        store4(g_CP + off, CP, lane);
        float c2p = vnorm2<4>(CP);
        if (lane == 0) g_c2P[n] = c2p;
    }
    // ---- Sphere cell ----
    {
        float mc[4]; load4(mc, c2 + off, lane);
        load4(t, g_Yc2 + off, lane);
        expmap0v<4>(e, t, KSC); logmap0v<4>(t, e, KSC);
#pragma unroll
        for (int i = 0; i < 4; i++) t[i] = tanh_f(t[i]);
        float csk[4]; expmap0v<4>(csk, t, KSC);
        float pw[4]; pwscalv<4>(pw, csk, g, KSC);
        float neg[4];
#pragma unroll
        for (int i = 0; i < 4; i++) neg[i] = -csk[i];
        float m1[4]; maddv<4>(m1, neg, mc, KSC);
        float ckt[4]; maddv<4>(ckt, m1, pw, KSC);
        load4(t, g_Yuf2 + off, lane);
        expmap0v<4>(e, t, KSC); logmap0v<4>(t, e, KSC);
        float f[4];
#pragma unroll
        for (int i = 0; i < 4; i++) f[i] = sigf(t[i]);
        float CS[4]; pwmulv<4>(CS, f, ckt, KSC);
        store4(g_CS + off, CS, lane);
        float c2s = vnorm2<4>(CS);
        if (lane == 0) g_c2S[n] = c2s;
    }
    // ---- Euclidean cell ----
    {
        float mc[4]; load4(mc, c3 + off, lane);
        load4(t, g_Yc3 + off, lane);
        float CE[4];
#pragma unroll
        for (int i = 0; i < 4; i++) {
            float csk = tanh_f(t[i]);
            CE[i] = mc[i] - csk + csk * g;
        }
        load4(t, g_Yuf3 + off, lane);
#pragma unroll
        for (int i = 0; i < 4; i++) CE[i] *= sigf(t[i]);
        store4(g_CE + off, CE, lane);
    }
    // ---- dest-side queries ----
    {
        float q[4];
        load4(t, g_XQP + off, lane);
        expmap0v<4>(q, t, KPC);
        store4(g_X1P + off, q, lane);
        float x2 = vnorm2<4>(q);
        if (lane == 0) g_x2P[n] = x2;
        load4(t, g_XQS + off, lane);
        expmap0v<4>(q, t, KSC);
        store4(g_X1S + off, q, lane);
        x2 = vnorm2<4>(q);
        if (lane == 0) g_x2S[n] = x2;
    }
}

// ======================= S3a: attention (3 spaces) =======================
DEV void attn_hyp(size_t off, const int* jarr, const float* Xq, const float* x2t,
                  const float* Htab, const float* y2t, float kcur,
                  __nv_bfloat16* outH, __nv_bfloat16* outL, int n, int lane) {
    float xq[4]; load4(xq, Xq + off, lane);
    float x2 = x2t[n];
    float vh[8][4], y2r[8], sc[8], a[8];
#pragma unroll
    for (int k = 0; k < 8; k++) {
        int j = jarr[k];
        load4(vh[k], Htab + (size_t)j * HH, lane);
        y2r[k] = y2t[j];
        float p = vdot<4>(xq, vh[k]);
        sc[k] = -distk(x2, y2r[k], p, kcur);
    }
    softmax8(sc, a);
    float num[4] = {0, 0, 0, 0};
    float ds = 0.f;
#pragma unroll
    for (int k = 0; k < 8; k++) {
        float lam = 2.f / (1.f + kcur * y2r[k]);
#pragma unroll
        for (int t = 0; t < 4; t++) num[t] = fmaf(a[k] * lam, vh[k][t], num[t]);
        ds += a[k] * (lam - 1.f);
    }
    float inv = 1.f / fmaxf(fabsf(ds), EPSV);
    float r[4];
#pragma unroll
    for (int t = 0; t < 4; t++) r[t] = num[t] * inv;
    float ht[4]; smulv<4>(ht, 0.5f, r, kcur);
    float lt[4]; logmap0v<4>(lt, ht, kcur);
    store4bf(outH + off, outL + off, lt, lane);
}

__global__ __launch_bounds__(256) void s3a_attn(const int* __restrict__ nbr) {
    int n = (blockIdx.x * 256 + threadIdx.x) >> 5;
    if (n >= NN) return;
    int lane = threadIdx.x & 31;
    size_t off = (size_t)n * HH;
    int jarr[8];
#pragma unroll
    for (int k = 0; k < 8; k++) jarr[k] = nbr[n * 8 + k];

    attn_hyp(off, jarr, g_X1P, g_x2P, g_HP, g_y2P, KPC, b_TPh, b_TPl, n, lane);
    attn_hyp(off, jarr, g_X1S, g_x2S, g_HS, g_y2S, KSC, b_TSh, b_TSl, n, lane);

    // Euclidean attention
    {
        float xq[4]; load4(xq, g_XQE + off, lane);
        float vh[8][4], sc[8], a[8];
#pragma unroll
        for (int k = 0; k < 8; k++) {
            load4(vh[k], g_HE + (size_t)jarr[k] * HH, lane);
            sc[k] = vdot<4>(xq, vh[k]) * 0.08838834764831845f;  // 1/sqrt(128)
        }
        softmax8(sc, a);
        float he[4] = {0, 0, 0, 0};
#pragma unroll
        for (int k = 0; k < 8; k++)
#pragma unroll
            for (int t = 0; t < 4; t++) he[t] = fmaf(a[k], vh[k][t], he[t]);
        store4bf(b_TEh + off, b_TEl + off, he, lane);
    }
}

// ======================= S3b: cell midpoints =======================
DEV void cellmid(size_t off, const int* jarr, const float* Ctab, const float* c2t,
                 float kcur, float* outC, int lane) {
    float num[4] = {0, 0, 0, 0};
    float ds = 0.f;
#pragma unroll
    for (int k = 0; k < 8; k++) {
        int j = jarr[k];
        float cv[4]; load4(cv, Ctab + (size_t)j * HH, lane);
        float lam = 2.f / (1.f + kcur * c2t[j]);
#pragma unroll
        for (int t = 0; t < 4; t++) num[t] = fmaf(lam, cv[t], num[t]);
        ds += lam - 1.f;
    }
    float inv = 1.f / fmaxf(fabsf(ds), EPSV);
    float r[4];
#pragma unroll
    for (int t = 0; t < 4; t++) r[t] = num[t] * inv;
    float o[4]; smulv<4>(o, 0.5f, r, kcur);
    store4(outC + off, o, lane);
}

__global__ __launch_bounds__(256) void s3b_cell(const int* __restrict__ nbr) {
    int n = (blockIdx.x * 256 + threadIdx.x) >> 5;
    if (n >= NN) return;
    int lane = threadIdx.x & 31;
    size_t off = (size_t)n * HH;
    int jarr[8];
#pragma unroll
    for (int k = 0; k < 8; k++) jarr[k] = nbr[n * 8 + k];

    cellmid(off, jarr, g_CP, g_c2P, KPC, g_C1, lane);
    cellmid(off, jarr, g_CS, g_c2S, KSC, g_C2, lane);
    {
        float s[4] = {0, 0, 0, 0};
#pragma unroll
        for (int k = 0; k < 8; k++) {
            float cv[4]; load4(cv, g_CE + (size_t)jarr[k] * HH, lane);
#pragma unroll
            for (int t = 0; t < 4; t++) s[t] += cv[t];
        }
        store4(g_C3 + off, s, lane);
    }
}

// ======================= S5: final node update =======================
__global__ __launch_bounds__(128) void s5_final(const float* __restrict__ iou1,
                                                const float* __restrict__ iou2,
                                                const float* __restrict__ iou3,
                                                float* __restrict__ out) {
    int n = (blockIdx.x * 128 + threadIdx.x) >> 5;
    if (n >= NN) return;
    int lane = threadIdx.x & 31;
    size_t o384 = (size_t)n * 384, o128 = (size_t)n * HH;
    const size_t SL = (size_t)NN * HH;

    // ---- Poincare ----
    {
        float z[12], e[12], io[12], ni[12];
        load12(z, g_Zp + o384, lane);
        expmap0v<12>(e, z, KPC);
        load12(io, iou1 + o384, lane);
        maddv<12>(ni, io, e, KPC);
        float ip[4], op[4], up[4];
        logmap0v<4>(ip, ni + 0, KPC);
        logmap0v<4>(op, ni + 4, KPC);
        logmap0v<4>(up, ni + 8, KPC);
#pragma unroll
        for (int i = 0; i < 4; i++) { ip[i] = sigf(ip[i]); op[i] = sigf(op[i]); up[i] = tanh_f(up[i]); }
        float pu[4]; pwmulv<4>(pu, ip, up, KPC);
        float cv[4]; load4(cv, g_C1 + o128, lane);
        float nc[4]; maddv<4>(nc, pu, cv, KPC);
        float lg[4]; logmap0v<4>(lg, nc, KPC);
#pragma unroll
        for (int i = 0; i < 4; i++) lg[i] = tanh_f(lg[i]);
        float nh[4]; pwmulv<4>(nh, op, lg, KPC);
        store4(out + 0 * SL + o128, nh, lane);
        store4(out + 1 * SL + o128, nc, lane);
    }
    // ---- Sphere ----
    {
        float z[12], e[12], io[12], ni[12];
        load12(z, g_Zs + o384, lane);
        expmap0v<12>(e, z, KSC);
        load12(io, iou2 + o384, lane);
        maddv<12>(ni, io, e, KSC);
        float ip[4], op[4], up[4];
        logmap0v<4>(ip, ni + 0, KSC);
        logmap0v<4>(op, ni + 4, KSC);
        logmap0v<4>(up, ni + 8, KSC);
#pragma unroll
        for (int i = 0; i < 4; i++) { ip[i] = sigf(ip[i]); op[i] = sigf(op[i]); up[i] = tanh_f(up[i]); }
        float pu[4]; pwmulv<4>(pu, ip, up, KSC);
        float cv[4]; load4(cv, g_C2 + o128, lane);
        float nc[4]; maddv<4>(nc, pu, cv, KSC);
        float lg[4]; logmap0v<4>(lg, nc, KSC);
#pragma unroll
        for (int i = 0; i < 4; i++) lg[i] = tanh_f(lg[i]);
        float nh[4]; pwmulv<4>(nh, op, lg, KSC);
        store4(out + 2 * SL + o128, nh, lane);
        store4(out + 3 * SL + o128, nc, lane);
    }
    // ---- Euclidean ----
    {
        float z[12], io[12];
        load12(z, g_Ze + o384, lane);
        load12(io, iou3 + o384, lane);
        float cv[4]; load4(cv, g_C3 + o128, lane);
        float nc[4], nh[4];
#pragma unroll
        for (int i = 0; i < 4; i++) {
            float ie = sigf(io[i] + z[i]);
            float oe = sigf(io[i + 4] + z[i + 4]);
            float ue = tanh_f(io[i + 8] + z[i + 8]);
            nc[i] = ie * ue + cv[i];
            nh[i] = oe * tanh_f(nc[i]);
        }
        store4(out + 4 * SL + o128, nh, lane);
        store4(out + 5 * SL + o128, nc, lane);
    }
}

// ======================= launch =======================
#define SYM(var, sym) cudaGetSymbolAddress((void**)&var, sym)

extern "C" void kernel_launch(void* const* d_in, const int* in_sizes, int n_in,
                              void* d_out, int out_size) {
    const float* x     = (const float*)d_in[0];
    const float* h1    = (const float*)d_in[1];
    const float* c1    = (const float*)d_in[2];
    const float* h2    = (const float*)d_in[3];
    const float* c2    = (const float*)d_in[4];
    const float* h3    = (const float*)d_in[5];
    const float* c3    = (const float*)d_in[6];
    const float* del_t = (const float*)d_in[7];
    const float* iou1  = (const float*)d_in[8];
    const float* iou2  = (const float*)d_in[9];
    const float* iou3  = (const float*)d_in[10];
    const float* Wq_w  = (const float*)d_in[11];
    const float* Wq_b  = (const float*)d_in[12];
    const float* Wc_w  = (const float*)d_in[13];
    const float* Wc_b  = (const float*)d_in[14];
    const float* Uf_w  = (const float*)d_in[15];
    const float* Uf_b  = (const float*)d_in[16];
    const float* Up_w  = (const float*)d_in[17];
    const float* Up_b  = (const float*)d_in[18];
    const float* Uiou_w = (const float*)d_in[19];
    const float* Uiou_b = (const float*)d_in[20];
    const float* dsc   = (const float*)d_in[21];
    const int*   nbr   = (const int*)d_in[22];
    float* out = (float*)d_out;

    float *pYup1, *pYup2, *pYup3, *pYc1, *pYc2, *pYc3, *pYuf1, *pYuf2, *pYuf3;
    float *pXQP, *pXQS, *pXQE, *pZp, *pZs, *pZe;
    SYM(pYup1, g_Yup1); SYM(pYup2, g_Yup2); SYM(pYup3, g_Yup3);
    SYM(pYc1, g_Yc1);   SYM(pYc2, g_Yc2);   SYM(pYc3, g_Yc3);
    SYM(pYuf1, g_Yuf1); SYM(pYuf2, g_Yuf2); SYM(pYuf3, g_Yuf3);
    SYM(pXQP, g_XQP);   SYM(pXQS, g_XQS);   SYM(pXQE, g_XQE);
    SYM(pZp, g_Zp);     SYM(pZs, g_Zs);     SYM(pZe, g_Ze);

    __nv_bfloat16 *pLh1h, *pLh1l, *pLh2h, *pLh2l, *pLc1h, *pLc1l, *pLc2h, *pLc2l;
    __nv_bfloat16 *pXPh, *pXPl, *pXSh, *pXSl, *pxh, *pxl, *ph3h, *ph3l, *pc3h, *pc3l;
    __nv_bfloat16 *pTPh, *pTPl, *pTSh, *pTSl, *pTEh, *pTEl;
    __nv_bfloat16 *pWqh, *pWql, *pWch, *pWcl, *pUfh, *pUfl, *pUph, *pUpl, *pUih, *pUil;
    SYM(pLh1h, b_Lh1h); SYM(pLh1l, b_Lh1l); SYM(pLh2h, b_Lh2h); SYM(pLh2l, b_Lh2l);
    SYM(pLc1h, b_Lc1h); SYM(pLc1l, b_Lc1l); SYM(pLc2h, b_Lc2h); SYM(pLc2l, b_Lc2l);
    SYM(pXPh, b_XPh);   SYM(pXPl, b_XPl);   SYM(pXSh, b_XSh);   SYM(pXSl, b_XSl);
    SYM(pxh, b_xh);     SYM(pxl, b_xl);     SYM(ph3h, b_h3h);   SYM(ph3l, b_h3l);
    SYM(pc3h, b_c3h);   SYM(pc3l, b_c3l);
    SYM(pTPh, b_TPh);   SYM(pTPl, b_TPl);   SYM(pTSh, b_TSh);   SYM(pTSl, b_TSl);
    SYM(pTEh, b_TEh);   SYM(pTEl, b_TEl);
    SYM(pWqh, b_Wqh);   SYM(pWql, b_Wql);   SYM(pWch, b_Wch);   SYM(pWcl, b_Wcl);
    SYM(pUfh, b_Ufh);   SYM(pUfl, b_Ufl);   SYM(pUph, b_Uph);   SYM(pUpl, b_Upl);
    SYM(pUih, b_Uih);   SYM(pUil, b_Uil);

    cudaFuncSetAttribute(gemm_bf, cudaFuncAttributeMaxDynamicSharedMemorySize, SMEM_BYTES);

    // raw-input + weight conversion (independent of s0)
    CvtBatch cv;
    cv.j[0] = {x,      pxh,  pxl,  NN * HH};
    cv.j[1] = {h3,     ph3h, ph3l, NN * HH};
    cv.j[2] = {c3,     pc3h, pc3l, NN * HH};
    cv.j[3] = {Wq_w,   pWqh, pWql, 128 * 128};
    cv.j[4] = {Wc_w,   pWch, pWcl, 128 * 128};
    cv.j[5] = {Uf_w,   pUfh, pUfl, 128 * 128};
    cv.j[6] = {Up_w,   pUph, pUpl, 128 * 128};
    cv.j[7] = {Uiou_w, pUih, pUil, 384 * 128};
    cvtk<<<dim3(NN * HH / 4 / 256, 8), 256>>>(cv);

    s0_prep<<<NN / 8, 256>>>(x, h1, h2, c1, c2);

    GemmBatch ga;
    ga.p[0]  = {pLh1h, pLh1l, pUph, pUpl, Up_b, pYup1};
    ga.p[1]  = {pLh2h, pLh2l, pUph, pUpl, Up_b, pYup2};
    ga.p[2]  = {ph3h,  ph3l,  pUph, pUpl, Up_b, pYup3};
    ga.p[3]  = {pLc1h, pLc1l, pWch, pWcl, Wc_b, pYc1};
    ga.p[4]  = {pLc2h, pLc2l, pWch, pWcl, Wc_b, pYc2};
    ga.p[5]  = {pc3h,  pc3l,  pWch, pWcl, Wc_b, pYc3};
    ga.p[6]  = {pLh1h, pLh1l, pUfh, pUfl, Uf_b, pYuf1};
    ga.p[7]  = {pLh2h, pLh2l, pUfh, pUfl, Uf_b, pYuf2};
    ga.p[8]  = {ph3h,  ph3l,  pUfh, pUfl, Uf_b, pYuf3};
    ga.p[9]  = {pXPh,  pXPl,  pWqh, pWql, Wq_b, pXQP};
    ga.p[10] = {pXSh,  pXSl,  pWqh, pWql, Wq_b, pXQS};
    ga.p[11] = {pxh,   pxl,   pWqh, pWql, Wq_b, pXQE};
    gemm_bf<<<dim3(NN / 128, 2, 12), 256, SMEM_BYTES>>>(ga, 128);

    s2_node<<<NN / 8, 256>>>(h1, h2, h3, c1, c2, c3, del_t, dsc);
    s3a_attn<<<NN / 8, 256>>>(nbr);
    s3b_cell<<<NN / 8, 256>>>(nbr);

    GemmBatch gb;
    gb.p[0] = {pTPh, pTPl, pUih, pUil, Uiou_b, pZp};
    gb.p[1] = {pTSh, pTSl, pUih, pUil, Uiou_b, pZs};
    gb.p[2] = {pTEh, pTEl, pUih, pUil, Uiou_b, pZe};
    for (int i = 3; i < 12; i++) gb.p[i] = gb.p[0];
    gemm_bf<<<dim3(NN / 128, 6, 3), 256, SMEM_BYTES>>>(gb, 384);

    s5_final<<<NN / 4, 128>>>(iou1, iou2, iou3, out);
}

// round 12
// speedup vs baseline: 2.0610x; 1.2584x over previous
#include <cuda_runtime.h>
#include <cuda_bf16.h>
#include <math.h>
#include <stdint.h>

#define DEV __device__ __forceinline__

constexpr int   NN   = 8192;
constexpr int   HH   = 128;
constexpr float KPC  = -1.f;   // Poincare
constexpr float KSC  =  1.f;   // Sphere
constexpr float EPSV = 1e-6f;

// ======================= fast transcendentals =======================
DEV float tanh_f(float x) {
    float ax = fabsf(x);
    float t = __expf(-2.f * ax);
    float r = __fdividef(1.f - t, 1.f + t);
    return copysignf(r, x);
}
DEV float atanh_f(float x) {  // caller guarantees |x| <= 1-1e-5
    return 0.5f * __logf(__fdividef(1.f + x, 1.f - x));
}

// ======================= warp / vector helpers =======================
DEV float wsum(float v) {
#pragma unroll
    for (int o = 16; o; o >>= 1) v += __shfl_xor_sync(0xffffffffu, v, o);
    return v;
}
template <int V> DEV float vdot(const float* a, const float* b) {
    float s = 0.f;
#pragma unroll
    for (int t = 0; t < V; t++) s = fmaf(a[t], b[t], s);
    return wsum(s);
}
template <int V> DEV float vnorm2(const float* a) { return vdot<V>(a, a); }

DEV float tank(float u, float k) {
    if (k < 0.f) return tanh_f(u);
    u = fminf(fmaxf(u, -1.47079f), 1.47079f);
    return __tanf(u);
}
DEV float artank(float u, float k) {
    if (k < 0.f) {
        u = fminf(fmaxf(u, -1.f + 1e-5f), 1.f - 1e-5f);
        return atanh_f(u);
    }
    return atanf(u);
}
DEV float sigf(float x) { return __fdividef(1.f, 1.f + __expf(-x)); }
DEV float sdn(float d) { return (d >= 0.f) ? fmaxf(d, EPSV) : fminf(d, -EPSV); }

// All norm/scale math via rsqrt: n = (n2+eps)*rn,  1/n = rn.
template <int V> DEV void projv(float* x, float k) {
    if (k < 0.f) {
        float n2 = vnorm2<V>(x);
        float rn = rsqrtf(n2 + 1e-15f);
        float n = (n2 + 1e-15f) * rn;
        float m = 1.f - 1e-4f;
        float s = (n > m) ? (m * rn) : 1.f;
#pragma unroll
        for (int t = 0; t < V; t++) x[t] *= s;
    }
}
template <int V> DEV void expmap0v(float* o, const float* u, float k) {
    float n2 = vnorm2<V>(u);
    float rn = rsqrtf(n2 + 1e-15f);
    float n = (n2 + 1e-15f) * rn;
    float s = tank(n, k) * rn;
#pragma unroll
    for (int t = 0; t < V; t++) o[t] = s * u[t];
    projv<V>(o, k);
}
template <int V> DEV void logmap0v(float* o, const float* y, float k) {
    float n2 = vnorm2<V>(y);
    float rn = rsqrtf(n2 + 1e-15f);
    float n = (n2 + 1e-15f) * rn;
    float s = artank(n, k) * rn;
#pragma unroll
    for (int t = 0; t < V; t++) o[t] = s * y[t];
}
template <int V> DEV void maddv(float* o, const float* x, const float* y, float k) {
    float x2 = vnorm2<V>(x), y2 = vnorm2<V>(y), xy = vdot<V>(x, y);
    float A = 1.f - 2.f * k * xy - k * y2;
    float B = 1.f + k * x2;
    float den = 1.f - 2.f * k * xy + k * k * x2 * y2;
    float inv = __fdividef(1.f, sdn(den));
#pragma unroll
    for (int t = 0; t < V; t++) o[t] = (A * x[t] + B * y[t]) * inv;
    projv<V>(o, k);
}
template <int V> DEV void pwmulv(float* o, const float* w, const float* x, float k) {
    float wx[V];
#pragma unroll
    for (int t = 0; t < V; t++) wx[t] = w[t] * x[t];
    float nx2 = vnorm2<V>(x);
    float rnx = rsqrtf(nx2 + 1e-15f);
    float nx = (nx2 + 1e-15f) * rnx;
    float nw2 = vnorm2<V>(wx);
    float rnw = rsqrtf(nw2 + 1e-15f);
    float nwx = (nw2 + 1e-15f) * rnw;
    float s = tank(nwx * rnx * artank(nx, k), k) * rnw;
#pragma unroll
    for (int t = 0; t < V; t++) o[t] = s * wx[t];
    projv<V>(o, k);
}
template <int V> DEV void pwscalv(float* o, const float* w, float g, float k) {
    float wx[V];
#pragma unroll
    for (int t = 0; t < V; t++) wx[t] = w[t] * g;
    float g2 = g * g + 1e-15f;
    float rng = rsqrtf(g2);
    float nx = g2 * rng;
    float nw2 = vnorm2<V>(wx);
    float rnw = rsqrtf(nw2 + 1e-15f);
    float nwx = (nw2 + 1e-15f) * rnw;
    float s = tank(nwx * rng * artank(nx, k), k) * rnw;
#pragma unroll
    for (int t = 0; t < V; t++) o[t] = s * wx[t];
    projv<V>(o, k);
}
template <int V> DEV void smulv(float* o, float r, const float* x, float k) {
    float n2 = vnorm2<V>(x);
    float rn = rsqrtf(n2 + 1e-15f);
    float n = (n2 + 1e-15f) * rn;
    float s = tank(r * artank(n, k), k) * rn;
#pragma unroll
    for (int t = 0; t < V; t++) o[t] = s * x[t];
    projv<V>(o, k);
}
template <int V> DEV void wmid3v(float* o, const float* a, const float* b,
                                 const float* c, float k) {
    float la = __fdividef(2.f, 1.f + k * vnorm2<V>(a));
    float lb = __fdividef(2.f, 1.f + k * vnorm2<V>(b));
    float lc = __fdividef(2.f, 1.f + k * vnorm2<V>(c));
    float den = fabsf(la + lb + lc - 3.f);
    float inv = __fdividef(1.f, fmaxf(den, EPSV));
    float tmp[V];
#pragma unroll
    for (int t = 0; t < V; t++) tmp[t] = (la * a[t] + lb * b[t] + lc * c[t]) * inv;
    smulv<V>(o, 0.5f, tmp, k);
}

DEV void load4(float* v, const float* p, int lane) {
#pragma unroll
    for (int t = 0; t < 4; t++) v[t] = p[lane + 32 * t];
}
DEV void store4(float* p, const float* v, int lane) {
#pragma unroll
    for (int t = 0; t < 4; t++) p[lane + 32 * t] = v[t];
}
DEV void load12(float* v, const float* p, int lane) {
#pragma unroll
    for (int t = 0; t < 12; t++) v[t] = p[lane + 32 * t];
}
DEV void store4bf(__nv_bfloat16* hp, __nv_bfloat16* lp, const float* v, int lane) {
#pragma unroll
    for (int t = 0; t < 4; t++) {
        float x = v[t];
        __nv_bfloat16 h = __float2bfloat16(x);
        hp[lane + 32 * t] = h;
        lp[lane + 32 * t] = __float2bfloat16(x - __bfloat162float(h));
    }
}

// dist(x,y,k) = 2*artan_k(||proj(mobius_add(-x,y,k))||).  p = dot(x,y).
DEV float distk(float x2, float y2, float p, float k) {
    float A = 1.f + 2.f * k * p - k * y2;     // coeff of (-x)
    float B = 1.f + k * x2;                   // coeff of y
    float den = 1.f + 2.f * k * p + k * k * x2 * y2;
    float rd = __fdividef(1.f, sdn(den));
    float q2 = fmaxf(A * A * x2 - 2.f * A * B * p + B * B * y2, 0.f) * rd * rd;
    if (k < 0.f) {
        float rq = rsqrtf(q2 + 1e-15f);
        float n = (q2 + 1e-15f) * rq;
        float m = 1.f - 1e-4f;
        if (n > m) { float s = m * rq; q2 *= s * s; }
        float rq2 = rsqrtf(q2 + 1e-15f);
        float nf = (q2 + 1e-15f) * rq2;
        nf = fminf(nf, 1.f - 1e-5f);
        return 2.f * atanh_f(nf);
    }
    float rq = rsqrtf(q2 + 1e-15f);
    float nf = (q2 + 1e-15f) * rq;
    return 2.f * atanf(nf);
}

DEV void softmax8(const float* s, float* a) {
    float m = s[0];
#pragma unroll
    for (int q = 1; q < 8; q++) m = fmaxf(m, s[q]);
    float sum = 0.f;
#pragma unroll
    for (int q = 0; q < 8; q++) { a[q] = __expf(s[q] - m); sum += a[q]; }
    float inv = __fdividef(1.f, sum);
#pragma unroll
    for (int q = 0; q < 8; q++) a[q] *= inv;
}

// ======================= device scratch =======================
__device__ float g_Lh1[NN * HH], g_Lh2[NN * HH];
__device__ float g_Yup1[NN * HH], g_Yup2[NN * HH], g_Yup3[NN * HH];
__device__ float g_Yc1[NN * HH],  g_Yc2[NN * HH],  g_Yc3[NN * HH];
__device__ float g_Yuf1[NN * HH], g_Yuf2[NN * HH], g_Yuf3[NN * HH];
__device__ float g_XQP[NN * HH],  g_XQS[NN * HH],  g_XQE[NN * HH];
__device__ float g_HP[NN * HH], g_HS[NN * HH], g_HE[NN * HH];
__device__ float g_CP[NN * HH], g_CS[NN * HH], g_CE[NN * HH];
__device__ float g_X1P[NN * HH], g_X1S[NN * HH];
__device__ float g_C1[NN * HH], g_C2[NN * HH], g_C3[NN * HH];
__device__ float g_Zp[NN * 384], g_Zs[NN * 384], g_Ze[NN * 384];
__device__ float g_y2P[NN], g_y2S[NN], g_c2P[NN], g_c2S[NN], g_x2P[NN], g_x2S[NN];

// bf16 hi/lo GEMM inputs
__device__ __nv_bfloat16 b_Lh1h[NN*HH], b_Lh1l[NN*HH], b_Lh2h[NN*HH], b_Lh2l[NN*HH];
__device__ __nv_bfloat16 b_Lc1h[NN*HH], b_Lc1l[NN*HH], b_Lc2h[NN*HH], b_Lc2l[NN*HH];
__device__ __nv_bfloat16 b_XPh[NN*HH],  b_XPl[NN*HH],  b_XSh[NN*HH],  b_XSl[NN*HH];
__device__ __nv_bfloat16 b_xh[NN*HH],   b_xl[NN*HH];
__device__ __nv_bfloat16 b_h3h[NN*HH],  b_h3l[NN*HH],  b_c3h[NN*HH],  b_c3l[NN*HH];
__device__ __nv_bfloat16 b_TPh[NN*HH],  b_TPl[NN*HH],  b_TSh[NN*HH],  b_TSl[NN*HH];
__device__ __nv_bfloat16 b_TEh[NN*HH],  b_TEl[NN*HH];
__device__ __nv_bfloat16 b_Wqh[128*128], b_Wql[128*128], b_Wch[128*128], b_Wcl[128*128];
__device__ __nv_bfloat16 b_Ufh[128*128], b_Ufl[128*128], b_Uph[128*128], b_Upl[128*128];
__device__ __nv_bfloat16 b_Uih[384*128], b_Uil[384*128];

// ======================= cvt pass: fp32 -> bf16 hi/lo =======================
struct CvtJob { const float* s; __nv_bfloat16* h; __nv_bfloat16* l; int n; };
struct CvtBatch { CvtJob j[8]; };

__global__ __launch_bounds__(256) void cvtk(CvtBatch cb) {
    CvtJob jb = cb.j[blockIdx.y];
    int i = (blockIdx.x * 256 + threadIdx.x) * 4;
    if (i >= jb.n) return;
    float4 v = *(const float4*)(jb.s + i);
    float vv[4] = {v.x, v.y, v.z, v.w};
#pragma unroll
    for (int t = 0; t < 4; t++) {
        __nv_bfloat16 h = __float2bfloat16(vv[t]);
        jb.h[i + t] = h;
        jb.l[i + t] = __float2bfloat16(vv[t] - __bfloat162float(h));
    }
}

// ======================= S0: logmap prep =======================
__global__ __launch_bounds__(256) void s0_prep(const float* __restrict__ x,
                                               const float* __restrict__ h1,
                                               const float* __restrict__ h2,
                                               const float* __restrict__ c1,
                                               const float* __restrict__ c2) {
    int n = (blockIdx.x * 256 + threadIdx.x) >> 5;
    if (n >= NN) return;
    int lane = threadIdx.x & 31;
    size_t off = (size_t)n * HH;
    float v[4], e[4], o[4];
    load4(v, x + off, lane);
    expmap0v<4>(e, v, KPC); logmap0v<4>(o, e, KPC); store4bf(b_XPh + off, b_XPl + off, o, lane);
    expmap0v<4>(e, v, KSC); logmap0v<4>(o, e, KSC); store4bf(b_XSh + off, b_XSl + off, o, lane);
    load4(v, h1 + off, lane); logmap0v<4>(o, v, KPC);
    store4(g_Lh1 + off, o, lane); store4bf(b_Lh1h + off, b_Lh1l + off, o, lane);
    load4(v, h2 + off, lane); logmap0v<4>(o, v, KSC);
    store4(g_Lh2 + off, o, lane); store4bf(b_Lh2h + off, b_Lh2l + off, o, lane);
    load4(v, c1 + off, lane); logmap0v<4>(o, v, KPC); store4bf(b_Lc1h + off, b_Lc1l + off, o, lane);
    load4(v, c2 + off, lane); logmap0v<4>(o, v, KSC); store4bf(b_Lc2h + off, b_Lc2l + off, o, lane);
}

// ======================= bf16 split tensor-core GEMM =======================
struct GemmDesc {
    const __nv_bfloat16 *Ah, *Al, *Wh, *Wl;
    const float* bias; float* C;
};
struct GemmBatch { GemmDesc p[12]; };

constexpr int RS = 136;          // smem row stride in bf16 (272B, conflict-free)
constexpr int SM_AH = 0;
constexpr int SM_AL = 128 * RS;
constexpr int SM_WH = 2 * 128 * RS;
constexpr int SM_WL = 2 * 128 * RS + 64 * RS;
constexpr int SMEM_ELEMS = 2 * 128 * RS + 2 * 64 * RS;   // 52224 bf16
constexpr int SMEM_BYTES = SMEM_ELEMS * 2;               // 104448 B

DEV uint32_t lds32(const __nv_bfloat16* p) { return *(const uint32_t*)p; }

DEV void mma_bf(float* d, const uint32_t* a, const uint32_t* b) {
    asm volatile(
        "mma.sync.aligned.m16n8k16.row.col.f32.bf16.bf16.f32 "
        "{%0,%1,%2,%3}, {%4,%5,%6,%7}, {%8,%9}, {%0,%1,%2,%3};"
        : "+f"(d[0]), "+f"(d[1]), "+f"(d[2]), "+f"(d[3])
        : "r"(a[0]), "r"(a[1]), "r"(a[2]), "r"(a[3]), "r"(b[0]), "r"(b[1]));
}

__global__ __launch_bounds__(256) void gemm_bf(GemmBatch gb, int NO) {
    extern __shared__ __align__(16) __nv_bfloat16 sm[];
    GemmDesc d = gb.p[blockIdx.z];
    int tid = threadIdx.x;
    int warp = tid >> 5, lane = tid & 31;
    int g = lane >> 2, t = lane & 3;
    int m0 = blockIdx.x * 128, n0 = blockIdx.y * 64;

#pragma unroll
    for (int it = 0; it < 8; it++) {
        int idx = tid + it * 256;
        int r = idx >> 4, c = idx & 15;
        *(uint4*)(sm + SM_AH + r * RS + c * 8) =
            *(const uint4*)(d.Ah + (size_t)(m0 + r) * 128 + c * 8);
        *(uint4*)(sm + SM_AL + r * RS + c * 8) =
            *(const uint4*)(d.Al + (size_t)(m0 + r) * 128 + c * 8);
    }
#pragma unroll
    for (int it = 0; it < 4; it++) {
        int idx = tid + it * 256;
        int r = idx >> 4, c = idx & 15;
        *(uint4*)(sm + SM_WH + r * RS + c * 8) =
            *(const uint4*)(d.Wh + (size_t)(n0 + r) * 128 + c * 8);
        *(uint4*)(sm + SM_WL + r * RS + c * 8) =
            *(const uint4*)(d.Wl + (size_t)(n0 + r) * 128 + c * 8);
    }
    __syncthreads();

    float acc[8][4] = {};
    int rowA = warp * 16 + g;
    const __nv_bfloat16* pa0h = sm + SM_AH + rowA * RS + 2 * t;
    const __nv_bfloat16* pa0l = sm + SM_AL + rowA * RS + 2 * t;

#pragma unroll
    for (int ks = 0; ks < 8; ks++) {
        int kb = ks * 16;
        uint32_t ah[4] = { lds32(pa0h + kb),            lds32(pa0h + 8 * RS + kb),
                           lds32(pa0h + kb + 8),        lds32(pa0h + 8 * RS + kb + 8) };
        uint32_t al[4] = { lds32(pa0l + kb),            lds32(pa0l + 8 * RS + kb),
                           lds32(pa0l + kb + 8),        lds32(pa0l + 8 * RS + kb + 8) };
#pragma unroll
        for (int nt = 0; nt < 8; nt++) {
            const __nv_bfloat16* pwh = sm + SM_WH + (nt * 8 + g) * RS + 2 * t + kb;
            const __nv_bfloat16* pwl = sm + SM_WL + (nt * 8 + g) * RS + 2 * t + kb;
            uint32_t bh[2] = { lds32(pwh), lds32(pwh + 8) };
            uint32_t bl[2] = { lds32(pwl), lds32(pwl + 8) };
            mma_bf(acc[nt], ah, bh);
            mma_bf(acc[nt], al, bh);
            mma_bf(acc[nt], ah, bl);
        }
    }

#pragma unroll
    for (int nt = 0; nt < 8; nt++) {
        int col = n0 + nt * 8 + 2 * t;
        float bi0 = d.bias[col], bi1 = d.bias[col + 1];
        size_t r0 = (size_t)(m0 + warp * 16 + g) * NO;
        size_t r1 = (size_t)(m0 + warp * 16 + g + 8) * NO;
        d.C[r0 + col]     = acc[nt][0] + bi0;
        d.C[r0 + col + 1] = acc[nt][1] + bi1;
        d.C[r1 + col]     = acc[nt][2] + bi0;
        d.C[r1 + col + 1] = acc[nt][3] + bi1;
    }
}

// ======================= S2: per-source-node stage =======================
__global__ __launch_bounds__(256) void s2_node(const float* __restrict__ h1,
                                               const float* __restrict__ h2,
                                               const float* __restrict__ h3,
                                               const float* __restrict__ c1,
                                               const float* __restrict__ c2,
                                               const float* __restrict__ c3,
                                               const float* __restrict__ del_t,
                                               const float* __restrict__ dscal) {
    int n = (blockIdx.x * 256 + threadIdx.x) >> 5;
    if (n >= NN) return;
    int lane = threadIdx.x & 31;
    size_t off = (size_t)n * HH;

    float mh1[4], mh2[4], mh3[4], lh1[4], lh2[4];
    load4(mh1, h1 + off, lane);
    load4(mh2, h2 + off, lane);
    load4(mh3, h3 + off, lane);
    load4(lh1, g_Lh1 + off, lane);
    load4(lh2, g_Lh2 + off, lane);

    float t[4], e[4], s1[4], s2v[4], s3v[4];
    load4(t, g_Yup1 + off, lane);
    expmap0v<4>(e, t, KPC);
#pragma unroll
    for (int i = 0; i < 4; i++) e[i] = sigf(e[i]);
    logmap0v<4>(s1, e, KPC);
    load4(t, g_Yup2 + off, lane);
    expmap0v<4>(e, t, KSC);
#pragma unroll
    for (int i = 0; i < 4; i++) e[i] = sigf(e[i]);
    logmap0v<4>(s2v, e, KSC);
    load4(t, g_Yup3 + off, lane);
#pragma unroll
    for (int i = 0; i < 4; i++) s3v[i] = sigf(t[i]);

    // ---- h_1p ----
    float ht1p[4], ht2p[4], ht3p[4], tmp[4], HP[4];
    pwmulv<4>(ht1p, s1, mh1, KPC);
    expmap0v<4>(tmp, lh2, KPC); pwmulv<4>(ht2p, s2v, tmp, KPC);
    expmap0v<4>(tmp, mh3, KPC); pwmulv<4>(ht3p, s3v, tmp, KPC);
    wmid3v<4>(HP, ht1p, ht2p, ht3p, KPC);
#pragma unroll
    for (int i = 0; i < 4; i++) HP[i] *= 3.f;
    store4(g_HP + off, HP, lane);
    float y2p = vnorm2<4>(HP);
    if (lane == 0) g_y2P[n] = y2p;

    // ---- h_1s ----
    float ht1s[4], ht2s[4], ht3s[4], HS[4];
    expmap0v<4>(tmp, lh1, KSC); pwmulv<4>(ht1s, s1, tmp, KPC);
    pwmulv<4>(ht2s, s2v, mh2, KSC);
    expmap0v<4>(tmp, mh3, KSC); pwmulv<4>(ht3s, s3v, tmp, KSC);
    wmid3v<4>(HS, ht1s, ht2s, ht3s, KPC);
#pragma unroll
    for (int i = 0; i < 4; i++) HS[i] *= 3.f;
    store4(g_HS + off, HS, lane);
    float y2s = vnorm2<4>(HS);
    if (lane == 0) g_y2S[n] = y2s;

    // ---- h_1e ----
    float he[4], l1[4], l2[4];
    logmap0v<4>(l1, ht1p, KPC);
    logmap0v<4>(l2, ht2s, KSC);
#pragma unroll
    for (int i = 0; i < 4; i++) he[i] = l1[i] + l2[i] + s3v[i] * mh3[i];
    store4(g_HE + off, he, lane);

    float g = __fdividef(dscal[0], del_t[n] + 1.f);

    // ---- Poincare cell ----
    {
        float mc[4]; load4(mc, c1 + off, lane);
        load4(t, g_Yc1 + off, lane);
        expmap0v<4>(e, t, KPC); logmap0v<4>(t, e, KPC);
#pragma unroll
        for (int i = 0; i < 4; i++) t[i] = tanh_f(t[i]);
        float csk[4]; expmap0v<4>(csk, t, KPC);
        float pw[4]; pwscalv<4>(pw, csk, g, KPC);
        float neg[4];
#pragma unroll
        for (int i = 0; i < 4; i++) neg[i] = -csk[i];
        float m1[4]; maddv<4>(m1, neg, mc, KPC);
        float ckt[4]; maddv<4>(ckt, m1, pw, KPC);
        load4(t, g_Yuf1 + off, lane);
        expmap0v<4>(e, t, KPC); logmap0v<4>(t, e, KPC);
        float f[4];
#pragma unroll
        for (int i = 0; i < 4; i++) f[i] = sigf(t[i]);
        float CP[4]; pwmulv<4>(CP, f, ckt, KPC);
        store4(g_CP + off, CP, lane);
        float c2p = vnorm2<4>(CP);
        if (lane == 0) g_c2P[n] = c2p;
    }
    // ---- Sphere cell ----
    {
        float mc[4]; load4(mc, c2 + off, lane);
        load4(t, g_Yc2 + off, lane);
        expmap0v<4>(e, t, KSC); logmap0v<4>(t, e, KSC);
#pragma unroll
        for (int i = 0; i < 4; i++) t[i] = tanh_f(t[i]);
        float csk[4]; expmap0v<4>(csk, t, KSC);
        float pw[4]; pwscalv<4>(pw, csk, g, KSC);
        float neg[4];
#pragma unroll
        for (int i = 0; i < 4; i++) neg[i] = -csk[i];
        float m1[4]; maddv<4>(m1, neg, mc, KSC);
        float ckt[4]; maddv<4>(ckt, m1, pw, KSC);
        load4(t, g_Yuf2 + off, lane);
        expmap0v<4>(e, t, KSC); logmap0v<4>(t, e, KSC);
        float f[4];
#pragma unroll
        for (int i = 0; i < 4; i++) f[i] = sigf(t[i]);
        float CS[4]; pwmulv<4>(CS, f, ckt, KSC);
        store4(g_CS + off, CS, lane);
        float c2s = vnorm2<4>(CS);
        if (lane == 0) g_c2S[n] = c2s;
    }
    // ---- Euclidean cell ----
    {
        float mc[4]; load4(mc, c3 + off, lane);
        load4(t, g_Yc3 + off, lane);
        float CE[4];
#pragma unroll
        for (int i = 0; i < 4; i++) {
            float csk = tanh_f(t[i]);
            CE[i] = mc[i] - csk + csk * g;
        }
        load4(t, g_Yuf3 + off, lane);
#pragma unroll
        for (int i = 0; i < 4; i++) CE[i] *= sigf(t[i]);
        store4(g_CE + off, CE, lane);
    }
    // ---- dest-side queries ----
    {
        float q[4];
        load4(t, g_XQP + off, lane);
        expmap0v<4>(q, t, KPC);
        store4(g_X1P + off, q, lane);
        float x2 = vnorm2<4>(q);
        if (lane == 0) g_x2P[n] = x2;
        load4(t, g_XQS + off, lane);
        expmap0v<4>(q, t, KSC);
        store4(g_X1S + off, q, lane);
        x2 = vnorm2<4>(q);
        if (lane == 0) g_x2S[n] = x2;
    }
}

// ======================= S3a: attention (3 spaces) =======================
DEV void attn_hyp(size_t off, const int* jarr, const float* Xq, const float* x2t,
                  const float* Htab, const float* y2t, float kcur,
                  __nv_bfloat16* outH, __nv_bfloat16* outL, int n, int lane) {
    float xq[4]; load4(xq, Xq + off, lane);
    float x2 = x2t[n];
    float vh[8][4], y2r[8], sc[8], a[8];
#pragma unroll
    for (int k = 0; k < 8; k++) {
        int j = jarr[k];
        load4(vh[k], Htab + (size_t)j * HH, lane);
        y2r[k] = y2t[j];
        float p = vdot<4>(xq, vh[k]);
        sc[k] = -distk(x2, y2r[k], p, kcur);
    }
    softmax8(sc, a);
    float num[4] = {0, 0, 0, 0};
    float ds = 0.f;
#pragma unroll
    for (int k = 0; k < 8; k++) {
        float lam = __fdividef(2.f, 1.f + kcur * y2r[k]);
#pragma unroll
        for (int t = 0; t < 4; t++) num[t] = fmaf(a[k] * lam, vh[k][t], num[t]);
        ds += a[k] * (lam - 1.f);
    }
    float inv = __fdividef(1.f, fmaxf(fabsf(ds), EPSV));
    float r[4];
#pragma unroll
    for (int t = 0; t < 4; t++) r[t] = num[t] * inv;
    float ht[4]; smulv<4>(ht, 0.5f, r, kcur);
    float lt[4]; logmap0v<4>(lt, ht, kcur);
    store4bf(outH + off, outL + off, lt, lane);
}

__global__ __launch_bounds__(256) void s3a_attn(const int* __restrict__ nbr) {
    int n = (blockIdx.x * 256 + threadIdx.x) >> 5;
    if (n >= NN) return;
    int lane = threadIdx.x & 31;
    size_t off = (size_t)n * HH;
    int jarr[8];
#pragma unroll
    for (int k = 0; k < 8; k++) jarr[k] = nbr[n * 8 + k];

    attn_hyp(off, jarr, g_X1P, g_x2P, g_HP, g_y2P, KPC, b_TPh, b_TPl, n, lane);
    attn_hyp(off, jarr, g_X1S, g_x2S, g_HS, g_y2S, KSC, b_TSh, b_TSl, n, lane);

    {
        float xq[4]; load4(xq, g_XQE + off, lane);
        float vh[8][4], sc[8], a[8];
#pragma unroll
        for (int k = 0; k < 8; k++) {
            load4(vh[k], g_HE + (size_t)jarr[k] * HH, lane);
            sc[k] = vdot<4>(xq, vh[k]) * 0.08838834764831845f;  // 1/sqrt(128)
        }
        softmax8(sc, a);
        float he[4] = {0, 0, 0, 0};
#pragma unroll
        for (int k = 0; k < 8; k++)
#pragma unroll
            for (int t = 0; t < 4; t++) he[t] = fmaf(a[k], vh[k][t], he[t]);
        store4bf(b_TEh + off, b_TEl + off, he, lane);
    }
}

// ======================= S3b: cell midpoints =======================
DEV void cellmid(size_t off, const int* jarr, const float* Ctab, const float* c2t,
                 float kcur, float* outC, int lane) {
    float num[4] = {0, 0, 0, 0};
    float ds = 0.f;
#pragma unroll
    for (int k = 0; k < 8; k++) {
        int j = jarr[k];
        float cv[4]; load4(cv, Ctab + (size_t)j * HH, lane);
        float lam = __fdividef(2.f, 1.f + kcur * c2t[j]);
#pragma unroll
        for (int t = 0; t < 4; t++) num[t] = fmaf(lam, cv[t], num[t]);
        ds += lam - 1.f;
    }
    float inv = __fdividef(1.f, fmaxf(fabsf(ds), EPSV));
    float r[4];
#pragma unroll
    for (int t = 0; t < 4; t++) r[t] = num[t] * inv;
    float o[4]; smulv<4>(o, 0.5f, r, kcur);
    store4(outC + off, o, lane);
}

__global__ __launch_bounds__(256) void s3b_cell(const int* __restrict__ nbr) {
    int n = (blockIdx.x * 256 + threadIdx.x) >> 5;
    if (n >= NN) return;
    int lane = threadIdx.x & 31;
    size_t off = (size_t)n * HH;
    int jarr[8];
#pragma unroll
    for (int k = 0; k < 8; k++) jarr[k] = nbr[n * 8 + k];

    cellmid(off, jarr, g_CP, g_c2P, KPC, g_C1, lane);
    cellmid(off, jarr, g_CS, g_c2S, KSC, g_C2, lane);
    {
        float s[4] = {0, 0, 0, 0};
#pragma unroll
        for (int k = 0; k < 8; k++) {
            float cv[4]; load4(cv, g_CE + (size_t)jarr[k] * HH, lane);
#pragma unroll
            for (int t = 0; t < 4; t++) s[t] += cv[t];
        }
        store4(g_C3 + off, s, lane);
    }
}

// ======================= S5: final node update =======================
__global__ __launch_bounds__(128) void s5_final(const float* __restrict__ iou1,
                                                const float* __restrict__ iou2,
                                                const float* __restrict__ iou3,
                                                float* __restrict__ out) {
    int n = (blockIdx.x * 128 + threadIdx.x) >> 5;
    if (n >= NN) return;
    int lane = threadIdx.x & 31;
    size_t o384 = (size_t)n * 384, o128 = (size_t)n * HH;
    const size_t SL = (size_t)NN * HH;

    // ---- Poincare ----
    {
        float z[12], e[12], io[12], ni[12];
        load12(z, g_Zp + o384, lane);
        expmap0v<12>(e, z, KPC);
        load12(io, iou1 + o384, lane);
        maddv<12>(ni, io, e, KPC);
        float ip[4], op[4], up[4];
        logmap0v<4>(ip, ni + 0, KPC);
        logmap0v<4>(op, ni + 4, KPC);
        logmap0v<4>(up, ni + 8, KPC);
#pragma unroll
        for (int i = 0; i < 4; i++) { ip[i] = sigf(ip[i]); op[i] = sigf(op[i]); up[i] = tanh_f(up[i]); }
        float pu[4]; pwmulv<4>(pu, ip, up, KPC);
        float cv[4]; load4(cv, g_C1 + o128, lane);
        float nc[4]; maddv<4>(nc, pu, cv, KPC);
        float lg[4]; logmap0v<4>(lg, nc, KPC);
#pragma unroll
        for (int i = 0; i < 4; i++) lg[i] = tanh_f(lg[i]);
        float nh[4]; pwmulv<4>(nh, op, lg, KPC);
        store4(out + 0 * SL + o128, nh, lane);
        store4(out + 1 * SL + o128, nc, lane);
    }
    // ---- Sphere ----
    {
        float z[12], e[12], io[12], ni[12];
        load12(z, g_Zs + o384, lane);
        expmap0v<12>(e, z, KSC);
        load12(io, iou2 + o384, lane);
        maddv<12>(ni, io, e, KSC);
        float ip[4], op[4], up[4];
        logmap0v<4>(ip, ni + 0, KSC);
        logmap0v<4>(op, ni + 4, KSC);
        logmap0v<4>(up, ni + 8, KSC);
#pragma unroll
        for (int i = 0; i < 4; i++) { ip[i] = sigf(ip[i]); op[i] = sigf(op[i]); up[i] = tanh_f(up[i]); }
        float pu[4]; pwmulv<4>(pu, ip, up, KSC);
        float cv[4]; load4(cv, g_C2 + o128, lane);
        float nc[4]; maddv<4>(nc, pu, cv, KSC);
        float lg[4]; logmap0v<4>(lg, nc, KSC);
#pragma unroll
        for (int i = 0; i < 4; i++) lg[i] = tanh_f(lg[i]);
        float nh[4]; pwmulv<4>(nh, op, lg, KSC);
        store4(out + 2 * SL + o128, nh, lane);
        store4(out + 3 * SL + o128, nc, lane);
    }
    // ---- Euclidean ----
    {
        float z[12], io[12];
        load12(z, g_Ze + o384, lane);
        load12(io, iou3 + o384, lane);
        float cv[4]; load4(cv, g_C3 + o128, lane);
        float nc[4], nh[4];
#pragma unroll
        for (int i = 0; i < 4; i++) {
            float ie = sigf(io[i] + z[i]);
            float oe = sigf(io[i + 4] + z[i + 4]);
            float ue = tanh_f(io[i + 8] + z[i + 8]);
            nc[i] = ie * ue + cv[i];
            nh[i] = oe * tanh_f(nc[i]);
        }
        store4(out + 4 * SL + o128, nh, lane);
        store4(out + 5 * SL + o128, nc, lane);
    }
}

// ======================= launch =======================
#define SYM(var, sym) cudaGetSymbolAddress((void**)&var, sym)

extern "C" void kernel_launch(void* const* d_in, const int* in_sizes, int n_in,
                              void* d_out, int out_size) {
    const float* x     = (const float*)d_in[0];
    const float* h1    = (const float*)d_in[1];
    const float* c1    = (const float*)d_in[2];
    const float* h2    = (const float*)d_in[3];
    const float* c2    = (const float*)d_in[4];
    const float* h3    = (const float*)d_in[5];
    const float* c3    = (const float*)d_in[6];
    const float* del_t = (const float*)d_in[7];
    const float* iou1  = (const float*)d_in[8];
    const float* iou2  = (const float*)d_in[9];
    const float* iou3  = (const float*)d_in[10];
    const float* Wq_w  = (const float*)d_in[11];
    const float* Wq_b  = (const float*)d_in[12];
    const float* Wc_w  = (const float*)d_in[13];
    const float* Wc_b  = (const float*)d_in[14];
    const float* Uf_w  = (const float*)d_in[15];
    const float* Uf_b  = (const float*)d_in[16];
    const float* Up_w  = (const float*)d_in[17];
    const float* Up_b  = (const float*)d_in[18];
    const float* Uiou_w = (const float*)d_in[19];
    const float* Uiou_b = (const float*)d_in[20];
    const float* dsc   = (const float*)d_in[21];
    const int*   nbr   = (const int*)d_in[22];
    float* out = (float*)d_out;

    float *pYup1, *pYup2, *pYup3, *pYc1, *pYc2, *pYc3, *pYuf1, *pYuf2, *pYuf3;
    float *pXQP, *pXQS, *pXQE, *pZp, *pZs, *pZe;
    SYM(pYup1, g_Yup1); SYM(pYup2, g_Yup2); SYM(pYup3, g_Yup3);
    SYM(pYc1, g_Yc1);   SYM(pYc2, g_Yc2);   SYM(pYc3, g_Yc3);
    SYM(pYuf1, g_Yuf1); SYM(pYuf2, g_Yuf2); SYM(pYuf3, g_Yuf3);
    SYM(pXQP, g_XQP);   SYM(pXQS, g_XQS);   SYM(pXQE, g_XQE);
    SYM(pZp, g_Zp);     SYM(pZs, g_Zs);     SYM(pZe, g_Ze);

    __nv_bfloat16 *pLh1h, *pLh1l, *pLh2h, *pLh2l, *pLc1h, *pLc1l, *pLc2h, *pLc2l;
    __nv_bfloat16 *pXPh, *pXPl, *pXSh, *pXSl, *pxh, *pxl, *ph3h, *ph3l, *pc3h, *pc3l;
    __nv_bfloat16 *pTPh, *pTPl, *pTSh, *pTSl, *pTEh, *pTEl;
    __nv_bfloat16 *pWqh, *pWql, *pWch, *pWcl, *pUfh, *pUfl, *pUph, *pUpl, *pUih, *pUil;
    SYM(pLh1h, b_Lh1h); SYM(pLh1l, b_Lh1l); SYM(pLh2h, b_Lh2h); SYM(pLh2l, b_Lh2l);
    SYM(pLc1h, b_Lc1h); SYM(pLc1l, b_Lc1l); SYM(pLc2h, b_Lc2h); SYM(pLc2l, b_Lc2l);
    SYM(pXPh, b_XPh);   SYM(pXPl, b_XPl);   SYM(pXSh, b_XSh);   SYM(pXSl, b_XSl);
    SYM(pxh, b_xh);     SYM(pxl, b_xl);     SYM(ph3h, b_h3h);   SYM(ph3l, b_h3l);
    SYM(pc3h, b_c3h);   SYM(pc3l, b_c3l);
    SYM(pTPh, b_TPh);   SYM(pTPl, b_TPl);   SYM(pTSh, b_TSh);   SYM(pTSl, b_TSl);
    SYM(pTEh, b_TEh);   SYM(pTEl, b_TEl);
    SYM(pWqh, b_Wqh);   SYM(pWql, b_Wql);   SYM(pWch, b_Wch);   SYM(pWcl, b_Wcl);
    SYM(pUfh, b_Ufh);   SYM(pUfl, b_Ufl);   SYM(pUph, b_Uph);   SYM(pUpl, b_Upl);
    SYM(pUih, b_Uih);   SYM(pUil, b_Uil);

    cudaFuncSetAttribute(gemm_bf, cudaFuncAttributeMaxDynamicSharedMemorySize, SMEM_BYTES);

    CvtBatch cv;
    cv.j[0] = {x,      pxh,  pxl,  NN * HH};
    cv.j[1] = {h3,     ph3h, ph3l, NN * HH};
    cv.j[2] = {c3,     pc3h, pc3l, NN * HH};
    cv.j[3] = {Wq_w,   pWqh, pWql, 128 * 128};
    cv.j[4] = {Wc_w,   pWch, pWcl, 128 * 128};
    cv.j[5] = {Uf_w,   pUfh, pUfl, 128 * 128};
    cv.j[6] = {Up_w,   pUph, pUpl, 128 * 128};
    cv.j[7] = {Uiou_w, pUih, pUil, 384 * 128};
    cvtk<<<dim3(NN * HH / 4 / 256, 8), 256>>>(cv);

    s0_prep<<<NN / 8, 256>>>(x, h1, h2, c1, c2);

    GemmBatch ga;
    ga.p[0]  = {pLh1h, pLh1l, pUph, pUpl, Up_b, pYup1};
    ga.p[1]  = {pLh2h, pLh2l, pUph, pUpl, Up_b, pYup2};
    ga.p[2]  = {ph3h,  ph3l,  pUph, pUpl, Up_b, pYup3};
    ga.p[3]  = {pLc1h, pLc1l, pWch, pWcl, Wc_b, pYc1};
    ga.p[4]  = {pLc2h, pLc2l, pWch, pWcl, Wc_b, pYc2};
    ga.p[5]  = {pc3h,  pc3l,  pWch, pWcl, Wc_b, pYc3};
    ga.p[6]  = {pLh1h, pLh1l, pUfh, pUfl, Uf_b, pYuf1};
    ga.p[7]  = {pLh2h, pLh2l, pUfh, pUfl, Uf_b, pYuf2};
    ga.p[8]  = {ph3h,  ph3l,  pUfh, pUfl, Uf_b, pYuf3};
    ga.p[9]  = {pXPh,  pXPl,  pWqh, pWql, Wq_b, pXQP};
    ga.p[10] = {pXSh,  pXSl,  pWqh, pWql, Wq_b, pXQS};
    ga.p[11] = {pxh,   pxl,   pWqh, pWql, Wq_b, pXQE};
    gemm_bf<<<dim3(NN / 128, 2, 12), 256, SMEM_BYTES>>>(ga, 128);

    s2_node<<<NN / 8, 256>>>(h1, h2, h3, c1, c2, c3, del_t, dsc);
    s3a_attn<<<NN / 8, 256>>>(nbr);
    s3b_cell<<<NN / 8, 256>>>(nbr);

    GemmBatch gb;
    gb.p[0] = {pTPh, pTPl, pUih, pUil, Uiou_b, pZp};
    gb.p[1] = {pTSh, pTSl, pUih, pUil, Uiou_b, pZs};
    gb.p[2] = {pTEh, pTEl, pUih, pUil, Uiou_b, pZe};
    for (int i = 3; i < 12; i++) gb.p[i] = gb.p[0];
    gemm_bf<<<dim3(NN / 128, 6, 3), 256, SMEM_BYTES>>>(gb, 384);

    s5_final<<<NN / 4, 128>>>(iou1, iou2, iou3, out);
}

// round 14
// speedup vs baseline: 2.1023x; 1.0200x over previous
#include <cuda_runtime.h>
#include <cuda_bf16.h>
#include <math.h>
#include <stdint.h>

#define DEV __device__ __forceinline__

constexpr int   NN   = 8192;
constexpr int   HH   = 128;
constexpr float KPC  = -1.f;   // Poincare
constexpr float KSC  =  1.f;   // Sphere
constexpr float EPSV = 1e-6f;

// ======================= fast transcendentals =======================
DEV float tanh_f(float x) {
    float ax = fabsf(x);
    float t = __expf(-2.f * ax);
    float r = __fdividef(1.f - t, 1.f + t);
    return copysignf(r, x);
}
DEV float atanh_f(float x) {  // caller guarantees |x| <= 1-1e-5
    return 0.5f * __logf(__fdividef(1.f + x, 1.f - x));
}

// ======================= warp / vector helpers =======================
// L = lanes per logical vector (groups aligned within warp).
template <int L> DEV float wsum(float v) {
#pragma unroll
    for (int o = L / 2; o; o >>= 1) v += __shfl_xor_sync(0xffffffffu, v, o);
    return v;
}
template <int V, int L> DEV float vdot(const float* a, const float* b) {
    float s = 0.f;
#pragma unroll
    for (int t = 0; t < V; t++) s = fmaf(a[t], b[t], s);
    return wsum<L>(s);
}
template <int V, int L> DEV float vnorm2(const float* a) { return vdot<V, L>(a, a); }

DEV float tank(float u, float k) {
    if (k < 0.f) return tanh_f(u);
    u = fminf(fmaxf(u, -1.47079f), 1.47079f);
    return __tanf(u);
}
DEV float artank(float u, float k) {
    if (k < 0.f) {
        u = fminf(fmaxf(u, -1.f + 1e-5f), 1.f - 1e-5f);
        return atanh_f(u);
    }
    return atanf(u);
}
DEV float sigf(float x) { return __fdividef(1.f, 1.f + __expf(-x)); }
DEV float sdn(float d) { return (d >= 0.f) ? fmaxf(d, EPSV) : fminf(d, -EPSV); }

template <int V, int L> DEV void projv(float* x, float k) {
    if (k < 0.f) {
        float n2 = vnorm2<V, L>(x);
        float rn = rsqrtf(n2 + 1e-15f);
        float n = (n2 + 1e-15f) * rn;
        float m = 1.f - 1e-4f;
        float s = (n > m) ? (m * rn) : 1.f;
#pragma unroll
        for (int t = 0; t < V; t++) x[t] *= s;
    }
}
template <int V, int L> DEV void expmap0v(float* o, const float* u, float k) {
    float n2 = vnorm2<V, L>(u);
    float rn = rsqrtf(n2 + 1e-15f);
    float n = (n2 + 1e-15f) * rn;
    float s = tank(n, k) * rn;
#pragma unroll
    for (int t = 0; t < V; t++) o[t] = s * u[t];
    projv<V, L>(o, k);
}
template <int V, int L> DEV void logmap0v(float* o, const float* y, float k) {
    float n2 = vnorm2<V, L>(y);
    float rn = rsqrtf(n2 + 1e-15f);
    float n = (n2 + 1e-15f) * rn;
    float s = artank(n, k) * rn;
#pragma unroll
    for (int t = 0; t < V; t++) o[t] = s * y[t];
}
template <int V, int L> DEV void maddv(float* o, const float* x, const float* y, float k) {
    float x2 = vnorm2<V, L>(x), y2 = vnorm2<V, L>(y), xy = vdot<V, L>(x, y);
    float A = 1.f - 2.f * k * xy - k * y2;
    float B = 1.f + k * x2;
    float den = 1.f - 2.f * k * xy + k * k * x2 * y2;
    float inv = __fdividef(1.f, sdn(den));
#pragma unroll
    for (int t = 0; t < V; t++) o[t] = (A * x[t] + B * y[t]) * inv;
    projv<V, L>(o, k);
}
template <int V, int L> DEV void pwmulv(float* o, const float* w, const float* x, float k) {
    float wx[V];
#pragma unroll
    for (int t = 0; t < V; t++) wx[t] = w[t] * x[t];
    float nx2 = vnorm2<V, L>(x);
    float rnx = rsqrtf(nx2 + 1e-15f);
    float nx = (nx2 + 1e-15f) * rnx;
    float nw2 = vnorm2<V, L>(wx);
    float rnw = rsqrtf(nw2 + 1e-15f);
    float nwx = (nw2 + 1e-15f) * rnw;
    float s = tank(nwx * rnx * artank(nx, k), k) * rnw;
#pragma unroll
    for (int t = 0; t < V; t++) o[t] = s * wx[t];
    projv<V, L>(o, k);
}
template <int V, int L> DEV void pwscalv(float* o, const float* w, float g, float k) {
    float wx[V];
#pragma unroll
    for (int t = 0; t < V; t++) wx[t] = w[t] * g;
    float g2 = g * g + 1e-15f;
    float rng = rsqrtf(g2);
    float nx = g2 * rng;
    float nw2 = vnorm2<V, L>(wx);
    float rnw = rsqrtf(nw2 + 1e-15f);
    float nwx = (nw2 + 1e-15f) * rnw;
    float s = tank(nwx * rng * artank(nx, k), k) * rnw;
#pragma unroll
    for (int t = 0; t < V; t++) o[t] = s * wx[t];
    projv<V, L>(o, k);
}
template <int V, int L> DEV void smulv(float* o, float r, const float* x, float k) {
    float n2 = vnorm2<V, L>(x);
    float rn = rsqrtf(n2 + 1e-15f);
    float n = (n2 + 1e-15f) * rn;
    float s = tank(r * artank(n, k), k) * rn;
#pragma unroll
    for (int t = 0; t < V; t++) o[t] = s * x[t];
    projv<V, L>(o, k);
}
template <int V, int L> DEV void wmid3v(float* o, const float* a, const float* b,
                                        const float* c, float k) {
    float la = __fdividef(2.f, 1.f + k * vnorm2<V, L>(a));
    float lb = __fdividef(2.f, 1.f + k * vnorm2<V, L>(b));
    float lc = __fdividef(2.f, 1.f + k * vnorm2<V, L>(c));
    float den = fabsf(la + lb + lc - 3.f);
    float inv = __fdividef(1.f, fmaxf(den, EPSV));
    float tmp[V];
#pragma unroll
    for (int t = 0; t < V; t++) tmp[t] = (la * a[t] + lb * b[t] + lc * c[t]) * inv;
    smulv<V, L>(o, 0.5f, tmp, k);
}

template <int V, int L> DEV void loadv(float* v, const float* p, int lane) {
#pragma unroll
    for (int t = 0; t < V; t++) v[t] = p[lane + L * t];
}
template <int V, int L> DEV void storev(float* p, const float* v, int lane) {
#pragma unroll
    for (int t = 0; t < V; t++) p[lane + L * t] = v[t];
}
template <int V, int L> DEV void storebfv(__nv_bfloat16* hp, __nv_bfloat16* lp,
                                          const float* v, int lane) {
#pragma unroll
    for (int t = 0; t < V; t++) {
        float x = v[t];
        __nv_bfloat16 h = __float2bfloat16(x);
        hp[lane + L * t] = h;
        lp[lane + L * t] = __float2bfloat16(x - __bfloat162float(h));
    }
}

// dist(x,y,k) = 2*artan_k(||proj(mobius_add(-x,y,k))||).  p = dot(x,y).
DEV float distk(float x2, float y2, float p, float k) {
    float A = 1.f + 2.f * k * p - k * y2;     // coeff of (-x)
    float B = 1.f + k * x2;                   // coeff of y
    float den = 1.f + 2.f * k * p + k * k * x2 * y2;
    float rd = __fdividef(1.f, sdn(den));
    float q2 = fmaxf(A * A * x2 - 2.f * A * B * p + B * B * y2, 0.f) * rd * rd;
    if (k < 0.f) {
        float rq = rsqrtf(q2 + 1e-15f);
        float n = (q2 + 1e-15f) * rq;
        float m = 1.f - 1e-4f;
        if (n > m) { float s = m * rq; q2 *= s * s; }
        float rq2 = rsqrtf(q2 + 1e-15f);
        float nf = (q2 + 1e-15f) * rq2;
        nf = fminf(nf, 1.f - 1e-5f);
        return 2.f * atanh_f(nf);
    }
    float rq = rsqrtf(q2 + 1e-15f);
    float nf = (q2 + 1e-15f) * rq;
    return 2.f * atanf(nf);
}

DEV void softmax8(const float* s, float* a) {
    float m = s[0];
#pragma unroll
    for (int q = 1; q < 8; q++) m = fmaxf(m, s[q]);
    float sum = 0.f;
#pragma unroll
    for (int q = 0; q < 8; q++) { a[q] = __expf(s[q] - m); sum += a[q]; }
    float inv = __fdividef(1.f, sum);
#pragma unroll
    for (int q = 0; q < 8; q++) a[q] *= inv;
}

// ======================= device scratch =======================
__device__ float g_Lh1[NN * HH], g_Lh2[NN * HH];
__device__ float g_Yup1[NN * HH], g_Yup2[NN * HH], g_Yup3[NN * HH];
__device__ float g_Yc1[NN * HH],  g_Yc2[NN * HH],  g_Yc3[NN * HH];
__device__ float g_Yuf1[NN * HH], g_Yuf2[NN * HH], g_Yuf3[NN * HH];
__device__ float g_XQP[NN * HH],  g_XQS[NN * HH],  g_XQE[NN * HH];
__device__ float g_HP[NN * HH], g_HS[NN * HH], g_HE[NN * HH];
__device__ float g_CP[NN * HH], g_CS[NN * HH], g_CE[NN * HH];
__device__ float g_X1P[NN * HH], g_X1S[NN * HH];
__device__ float g_C1[NN * HH], g_C2[NN * HH], g_C3[NN * HH];
__device__ float g_Zp[NN * 384], g_Zs[NN * 384], g_Ze[NN * 384];
__device__ float g_y2P[NN], g_y2S[NN], g_c2P[NN], g_c2S[NN], g_x2P[NN], g_x2S[NN];

// bf16 hi/lo GEMM inputs
__device__ __nv_bfloat16 b_Lh1h[NN*HH], b_Lh1l[NN*HH], b_Lh2h[NN*HH], b_Lh2l[NN*HH];
__device__ __nv_bfloat16 b_Lc1h[NN*HH], b_Lc1l[NN*HH], b_Lc2h[NN*HH], b_Lc2l[NN*HH];
__device__ __nv_bfloat16 b_XPh[NN*HH],  b_XPl[NN*HH],  b_XSh[NN*HH],  b_XSl[NN*HH];
__device__ __nv_bfloat16 b_xh[NN*HH],   b_xl[NN*HH];
__device__ __nv_bfloat16 b_h3h[NN*HH],  b_h3l[NN*HH],  b_c3h[NN*HH],  b_c3l[NN*HH];
__device__ __nv_bfloat16 b_TPh[NN*HH],  b_TPl[NN*HH],  b_TSh[NN*HH],  b_TSl[NN*HH];
__device__ __nv_bfloat16 b_TEh[NN*HH],  b_TEl[NN*HH];
__device__ __nv_bfloat16 b_Wqh[128*128], b_Wql[128*128], b_Wch[128*128], b_Wcl[128*128];
__device__ __nv_bfloat16 b_Ufh[128*128], b_Ufl[128*128], b_Uph[128*128], b_Upl[128*128];
__device__ __nv_bfloat16 b_Uih[384*128], b_Uil[384*128];

// ======================= cvt pass: fp32 -> bf16 hi/lo =======================
struct CvtJob { const float* s; __nv_bfloat16* h; __nv_bfloat16* l; int n; };
struct CvtBatch { CvtJob j[8]; };

__global__ __launch_bounds__(256) void cvtk(CvtBatch cb) {
    CvtJob jb = cb.j[blockIdx.y];
    int i = (blockIdx.x * 256 + threadIdx.x) * 4;
    if (i >= jb.n) return;
    float4 v = *(const float4*)(jb.s + i);
    float vv[4] = {v.x, v.y, v.z, v.w};
#pragma unroll
    for (int t = 0; t < 4; t++) {
        __nv_bfloat16 h = __float2bfloat16(vv[t]);
        jb.h[i + t] = h;
        jb.l[i + t] = __float2bfloat16(vv[t] - __bfloat162float(h));
    }
}

// ======================= S0: logmap prep (16 lanes/node, V=8) ==============
__global__ __launch_bounds__(256) void s0_prep(const float* __restrict__ x,
                                               const float* __restrict__ h1,
                                               const float* __restrict__ h2,
                                               const float* __restrict__ c1,
                                               const float* __restrict__ c2) {
    int n = blockIdx.x * 16 + (threadIdx.x >> 4);
    if (n >= NN) return;
    int lane = threadIdx.x & 15;
    size_t off = (size_t)n * HH;
    float v[8], e[8], o[8];
    loadv<8,16>(v, x + off, lane);
    expmap0v<8,16>(e, v, KPC); logmap0v<8,16>(o, e, KPC); storebfv<8,16>(b_XPh + off, b_XPl + off, o, lane);
    expmap0v<8,16>(e, v, KSC); logmap0v<8,16>(o, e, KSC); storebfv<8,16>(b_XSh + off, b_XSl + off, o, lane);
    loadv<8,16>(v, h1 + off, lane); logmap0v<8,16>(o, v, KPC);
    storev<8,16>(g_Lh1 + off, o, lane); storebfv<8,16>(b_Lh1h + off, b_Lh1l + off, o, lane);
    loadv<8,16>(v, h2 + off, lane); logmap0v<8,16>(o, v, KSC);
    storev<8,16>(g_Lh2 + off, o, lane); storebfv<8,16>(b_Lh2h + off, b_Lh2l + off, o, lane);
    loadv<8,16>(v, c1 + off, lane); logmap0v<8,16>(o, v, KPC); storebfv<8,16>(b_Lc1h + off, b_Lc1l + off, o, lane);
    loadv<8,16>(v, c2 + off, lane); logmap0v<8,16>(o, v, KSC); storebfv<8,16>(b_Lc2h + off, b_Lc2l + off, o, lane);
}

// ======================= bf16 split tensor-core GEMM =======================
struct GemmDesc {
    const __nv_bfloat16 *Ah, *Al, *Wh, *Wl;
    const float* bias; float* C;
};
struct GemmBatch { GemmDesc p[12]; };

constexpr int RS = 136;          // smem row stride in bf16 (272B, conflict-free)
constexpr int SM_AH = 0;
constexpr int SM_AL = 128 * RS;
constexpr int SM_WH = 2 * 128 * RS;
constexpr int SM_WL = 2 * 128 * RS + 64 * RS;
constexpr int SMEM_ELEMS = 2 * 128 * RS + 2 * 64 * RS;   // 52224 bf16
constexpr int SMEM_BYTES = SMEM_ELEMS * 2;               // 104448 B

DEV uint32_t lds32(const __nv_bfloat16* p) { return *(const uint32_t*)p; }

DEV void mma_bf(float* d, const uint32_t* a, const uint32_t* b) {
    asm volatile(
        "mma.sync.aligned.m16n8k16.row.col.f32.bf16.bf16.f32 "
        "{%0,%1,%2,%3}, {%4,%5,%6,%7}, {%8,%9}, {%0,%1,%2,%3};"
        : "+f"(d[0]), "+f"(d[1]), "+f"(d[2]), "+f"(d[3])
        : "r"(a[0]), "r"(a[1]), "r"(a[2]), "r"(a[3]), "r"(b[0]), "r"(b[1]));
}

__global__ __launch_bounds__(256) void gemm_bf(GemmBatch gb, int NO) {
    extern __shared__ __align__(16) __nv_bfloat16 sm[];
    GemmDesc d = gb.p[blockIdx.z];
    int tid = threadIdx.x;
    int warp = tid >> 5, lane = tid & 31;
    int g = lane >> 2, t = lane & 3;
    int m0 = blockIdx.x * 128, n0 = blockIdx.y * 64;

#pragma unroll
    for (int it = 0; it < 8; it++) {
        int idx = tid + it * 256;
        int r = idx >> 4, c = idx & 15;
        *(uint4*)(sm + SM_AH + r * RS + c * 8) =
            *(const uint4*)(d.Ah + (size_t)(m0 + r) * 128 + c * 8);
        *(uint4*)(sm + SM_AL + r * RS + c * 8) =
            *(const uint4*)(d.Al + (size_t)(m0 + r) * 128 + c * 8);
    }
#pragma unroll
    for (int it = 0; it < 4; it++) {
        int idx = tid + it * 256;
        int r = idx >> 4, c = idx & 15;
        *(uint4*)(sm + SM_WH + r * RS + c * 8) =
            *(const uint4*)(d.Wh + (size_t)(n0 + r) * 128 + c * 8);
        *(uint4*)(sm + SM_WL + r * RS + c * 8) =
            *(const uint4*)(d.Wl + (size_t)(n0 + r) * 128 + c * 8);
    }
    __syncthreads();

    float acc[8][4] = {};
    int rowA = warp * 16 + g;
    const __nv_bfloat16* pa0h = sm + SM_AH + rowA * RS + 2 * t;
    const __nv_bfloat16* pa0l = sm + SM_AL + rowA * RS + 2 * t;

#pragma unroll
    for (int ks = 0; ks < 8; ks++) {
        int kb = ks * 16;
        uint32_t ah[4] = { lds32(pa0h + kb),            lds32(pa0h + 8 * RS + kb),
                           lds32(pa0h + kb + 8),        lds32(pa0h + 8 * RS + kb + 8) };
        uint32_t al[4] = { lds32(pa0l + kb),            lds32(pa0l + 8 * RS + kb),
                           lds32(pa0l + kb + 8),        lds32(pa0l + 8 * RS + kb + 8) };
#pragma unroll
        for (int nt = 0; nt < 8; nt++) {
            const __nv_bfloat16* pwh = sm + SM_WH + (nt * 8 + g) * RS + 2 * t + kb;
            const __nv_bfloat16* pwl = sm + SM_WL + (nt * 8 + g) * RS + 2 * t + kb;
            uint32_t bh[2] = { lds32(pwh), lds32(pwh + 8) };
            uint32_t bl[2] = { lds32(pwl), lds32(pwl + 8) };
            mma_bf(acc[nt], ah, bh);
            mma_bf(acc[nt], al, bh);
            mma_bf(acc[nt], ah, bl);
        }
    }

#pragma unroll
    for (int nt = 0; nt < 8; nt++) {
        int col = n0 + nt * 8 + 2 * t;
        float bi0 = d.bias[col], bi1 = d.bias[col + 1];
        size_t r0 = (size_t)(m0 + warp * 16 + g) * NO;
        size_t r1 = (size_t)(m0 + warp * 16 + g + 8) * NO;
        d.C[r0 + col]     = acc[nt][0] + bi0;
        d.C[r0 + col + 1] = acc[nt][1] + bi1;
        d.C[r1 + col]     = acc[nt][2] + bi0;
        d.C[r1 + col + 1] = acc[nt][3] + bi1;
    }
}

// ======================= S2: per-source-node stage (16 lanes/node, V=8) ====
__global__ __launch_bounds__(256) void s2_node(const float* __restrict__ h1,
                                               const float* __restrict__ h2,
                                               const float* __restrict__ h3,
                                               const float* __restrict__ c1,
                                               const float* __restrict__ c2,
                                               const float* __restrict__ c3,
                                               const float* __restrict__ del_t,
                                               const float* __restrict__ dscal) {
    int n = blockIdx.x * 16 + (threadIdx.x >> 4);
    if (n >= NN) return;
    int lane = threadIdx.x & 15;
    size_t off = (size_t)n * HH;

    float mh3[8], lh1[8], lh2[8];
    loadv<8,16>(mh3, h3 + off, lane);
    loadv<8,16>(lh1, g_Lh1 + off, lane);
    loadv<8,16>(lh2, g_Lh2 + off, lane);

    float t[8], e[8], s1[8], s2v[8], s3v[8];
    loadv<8,16>(t, g_Yup1 + off, lane);
    expmap0v<8,16>(e, t, KPC);
#pragma unroll
    for (int i = 0; i < 8; i++) e[i] = sigf(e[i]);
    logmap0v<8,16>(s1, e, KPC);
    loadv<8,16>(t, g_Yup2 + off, lane);
    expmap0v<8,16>(e, t, KSC);
#pragma unroll
    for (int i = 0; i < 8; i++) e[i] = sigf(e[i]);
    logmap0v<8,16>(s2v, e, KSC);
    loadv<8,16>(t, g_Yup3 + off, lane);
#pragma unroll
    for (int i = 0; i < 8; i++) s3v[i] = sigf(t[i]);

    // ---- h_1p ----
    float ht1p[8], ht2p[8], ht3p[8], tmp[8], HP[8];
    loadv<8,16>(t, h1 + off, lane);            // mh1
    pwmulv<8,16>(ht1p, s1, t, KPC);
    expmap0v<8,16>(tmp, lh2, KPC); pwmulv<8,16>(ht2p, s2v, tmp, KPC);
    expmap0v<8,16>(tmp, mh3, KPC); pwmulv<8,16>(ht3p, s3v, tmp, KPC);
    wmid3v<8,16>(HP, ht1p, ht2p, ht3p, KPC);
#pragma unroll
    for (int i = 0; i < 8; i++) HP[i] *= 3.f;
    storev<8,16>(g_HP + off, HP, lane);
    float y2p = vnorm2<8,16>(HP);
    if (lane == 0) g_y2P[n] = y2p;

    // ---- h_1s ----
    float ht2s[8], HS[8];
    {
        float ht1s[8], ht3s[8];
        expmap0v<8,16>(tmp, lh1, KSC); pwmulv<8,16>(ht1s, s1, tmp, KPC);
        loadv<8,16>(t, h2 + off, lane);        // mh2
        pwmulv<8,16>(ht2s, s2v, t, KSC);
        expmap0v<8,16>(tmp, mh3, KSC); pwmulv<8,16>(ht3s, s3v, tmp, KSC);
        wmid3v<8,16>(HS, ht1s, ht2s, ht3s, KPC);
    }
#pragma unroll
    for (int i = 0; i < 8; i++) HS[i] *= 3.f;
    storev<8,16>(g_HS + off, HS, lane);
    float y2s = vnorm2<8,16>(HS);
    if (lane == 0) g_y2S[n] = y2s;

    // ---- h_1e ----
    {
        float he[8], l1[8], l2[8];
        logmap0v<8,16>(l1, ht1p, KPC);
        logmap0v<8,16>(l2, ht2s, KSC);
#pragma unroll
        for (int i = 0; i < 8; i++) he[i] = l1[i] + l2[i] + s3v[i] * mh3[i];
        storev<8,16>(g_HE + off, he, lane);
    }

    float g = __fdividef(dscal[0], del_t[n] + 1.f);

    // ---- Poincare cell ----
    {
        float mc[8]; loadv<8,16>(mc, c1 + off, lane);
        loadv<8,16>(t, g_Yc1 + off, lane);
        expmap0v<8,16>(e, t, KPC); logmap0v<8,16>(t, e, KPC);
#pragma unroll
        for (int i = 0; i < 8; i++) t[i] = tanh_f(t[i]);
        float csk[8]; expmap0v<8,16>(csk, t, KPC);
        float pw[8]; pwscalv<8,16>(pw, csk, g, KPC);
        float neg[8];
#pragma unroll
        for (int i = 0; i < 8; i++) neg[i] = -csk[i];
        float m1[8]; maddv<8,16>(m1, neg, mc, KPC);
        float ckt[8]; maddv<8,16>(ckt, m1, pw, KPC);
        loadv<8,16>(t, g_Yuf1 + off, lane);
        expmap0v<8,16>(e, t, KPC); logmap0v<8,16>(t, e, KPC);
        float f[8];
#pragma unroll
        for (int i = 0; i < 8; i++) f[i] = sigf(t[i]);
        float CP[8]; pwmulv<8,16>(CP, f, ckt, KPC);
        storev<8,16>(g_CP + off, CP, lane);
        float c2p = vnorm2<8,16>(CP);
        if (lane == 0) g_c2P[n] = c2p;
    }
    // ---- Sphere cell ----
    {
        float mc[8]; loadv<8,16>(mc, c2 + off, lane);
        loadv<8,16>(t, g_Yc2 + off, lane);
        expmap0v<8,16>(e, t, KSC); logmap0v<8,16>(t, e, KSC);
#pragma unroll
        for (int i = 0; i < 8; i++) t[i] = tanh_f(t[i]);
        float csk[8]; expmap0v<8,16>(csk, t, KSC);
        float pw[8]; pwscalv<8,16>(pw, csk, g, KSC);
        float neg[8];
#pragma unroll
        for (int i = 0; i < 8; i++) neg[i] = -csk[i];
        float m1[8]; maddv<8,16>(m1, neg, mc, KSC);
        float ckt[8]; maddv<8,16>(ckt, m1, pw, KSC);
        loadv<8,16>(t, g_Yuf2 + off, lane);
        expmap0v<8,16>(e, t, KSC); logmap0v<8,16>(t, e, KSC);
        float f[8];
#pragma unroll
        for (int i = 0; i < 8; i++) f[i] = sigf(t[i]);
        float CS[8]; pwmulv<8,16>(CS, f, ckt, KSC);
        storev<8,16>(g_CS + off, CS, lane);
        float c2s = vnorm2<8,16>(CS);
        if (lane == 0) g_c2S[n] = c2s;
    }
    // ---- Euclidean cell ----
    {
        float mc[8]; loadv<8,16>(mc, c3 + off, lane);
        loadv<8,16>(t, g_Yc3 + off, lane);
        float CE[8];
#pragma unroll
        for (int i = 0; i < 8; i++) {
            float csk = tanh_f(t[i]);
            CE[i] = mc[i] - csk + csk * g;
        }
        loadv<8,16>(t, g_Yuf3 + off, lane);
#pragma unroll
        for (int i = 0; i < 8; i++) CE[i] *= sigf(t[i]);
        storev<8,16>(g_CE + off, CE, lane);
    }
    // ---- dest-side queries ----
    {
        float q[8];
        loadv<8,16>(t, g_XQP + off, lane);
        expmap0v<8,16>(q, t, KPC);
        storev<8,16>(g_X1P + off, q, lane);
        float x2 = vnorm2<8,16>(q);
        if (lane == 0) g_x2P[n] = x2;
        loadv<8,16>(t, g_XQS + off, lane);
        expmap0v<8,16>(q, t, KSC);
        storev<8,16>(g_X1S + off, q, lane);
        x2 = vnorm2<8,16>(q);
        if (lane == 0) g_x2S[n] = x2;
    }
}

// ======================= S3: gather + attention + cell midpoints ===========
DEV void attn_hyp(size_t off, const int* jarr, const float* Xq, const float* x2t,
                  const float* Htab, const float* y2t, float kcur,
                  __nv_bfloat16* outH, __nv_bfloat16* outL, int n, int lane) {
    float xq[4]; loadv<4,32>(xq, Xq + off, lane);
    float x2 = x2t[n];
    float vh[8][4], y2r[8], sc[8], a[8];
#pragma unroll
    for (int k = 0; k < 8; k++) {
        int j = jarr[k];
        loadv<4,32>(vh[k], Htab + (size_t)j * HH, lane);
        y2r[k] = y2t[j];
        float p = vdot<4,32>(xq, vh[k]);
        sc[k] = -distk(x2, y2r[k], p, kcur);
    }
    softmax8(sc, a);
    float num[4] = {0, 0, 0, 0};
    float ds = 0.f;
#pragma unroll
    for (int k = 0; k < 8; k++) {
        float lam = __fdividef(2.f, 1.f + kcur * y2r[k]);
#pragma unroll
        for (int t = 0; t < 4; t++) num[t] = fmaf(a[k] * lam, vh[k][t], num[t]);
        ds += a[k] * (lam - 1.f);
    }
    float inv = __fdividef(1.f, fmaxf(fabsf(ds), EPSV));
    float r[4];
#pragma unroll
    for (int t = 0; t < 4; t++) r[t] = num[t] * inv;
    float ht[4]; smulv<4,32>(ht, 0.5f, r, kcur);
    float lt[4]; logmap0v<4,32>(lt, ht, kcur);
    storebfv<4,32>(outH + off, outL + off, lt, lane);
}

DEV void cellmid(size_t off, const int* jarr, const float* Ctab, const float* c2t,
                 float kcur, float* outC, int lane) {
    float num[4] = {0, 0, 0, 0};
    float ds = 0.f;
#pragma unroll
    for (int k = 0; k < 8; k++) {
        int j = jarr[k];
        float cv[4]; loadv<4,32>(cv, Ctab + (size_t)j * HH, lane);
        float lam = __fdividef(2.f, 1.f + kcur * c2t[j]);
#pragma unroll
        for (int t = 0; t < 4; t++) num[t] = fmaf(lam, cv[t], num[t]);
        ds += lam - 1.f;
    }
    float inv = __fdividef(1.f, fmaxf(fabsf(ds), EPSV));
    float r[4];
#pragma unroll
    for (int t = 0; t < 4; t++) r[t] = num[t] * inv;
    float o[4]; smulv<4,32>(o, 0.5f, r, kcur);
    storev<4,32>(outC + off, o, lane);
}

__global__ __launch_bounds__(256) void s3_gather(const int* __restrict__ nbr) {
    int n = (blockIdx.x * 256 + threadIdx.x) >> 5;
    if (n >= NN) return;
    int lane = threadIdx.x & 31;
    size_t off = (size_t)n * HH;
    int jarr[8];
#pragma unroll
    for (int k = 0; k < 8; k++) jarr[k] = nbr[n * 8 + k];

    attn_hyp(off, jarr, g_X1P, g_x2P, g_HP, g_y2P, KPC, b_TPh, b_TPl, n, lane);
    attn_hyp(off, jarr, g_X1S, g_x2S, g_HS, g_y2S, KSC, b_TSh, b_TSl, n, lane);

    // Euclidean attention
    {
        float xq[4]; loadv<4,32>(xq, g_XQE + off, lane);
        float vh[8][4], sc[8], a[8];
#pragma unroll
        for (int k = 0; k < 8; k++) {
            loadv<4,32>(vh[k], g_HE + (size_t)jarr[k] * HH, lane);
            sc[k] = vdot<4,32>(xq, vh[k]) * 0.08838834764831845f;  // 1/sqrt(128)
        }
        softmax8(sc, a);
        float he[4] = {0, 0, 0, 0};
#pragma unroll
        for (int k = 0; k < 8; k++)
#pragma unroll
            for (int t = 0; t < 4; t++) he[t] = fmaf(a[k], vh[k][t], he[t]);
        storebfv<4,32>(b_TEh + off, b_TEl + off, he, lane);
    }

    cellmid(off, jarr, g_CP, g_c2P, KPC, g_C1, lane);
    cellmid(off, jarr, g_CS, g_c2S, KSC, g_C2, lane);

    // c_3 = sum_k CE(j)
    {
        float s[4] = {0, 0, 0, 0};
#pragma unroll
        for (int k = 0; k < 8; k++) {
            float cv[4]; loadv<4,32>(cv, g_CE + (size_t)jarr[k] * HH, lane);
#pragma unroll
            for (int t = 0; t < 4; t++) s[t] += cv[t];
        }
        storev<4,32>(g_C3 + off, s, lane);
    }
}

// ======================= S5: final node update =======================
__global__ __launch_bounds__(128) void s5_final(const float* __restrict__ iou1,
                                                const float* __restrict__ iou2,
                                                const float* __restrict__ iou3,
                                                float* __restrict__ out) {
    int n = (blockIdx.x * 128 + threadIdx.x) >> 5;
    if (n >= NN) return;
    int lane = threadIdx.x & 31;
    size_t o384 = (size_t)n * 384, o128 = (size_t)n * HH;
    const size_t SL = (size_t)NN * HH;

    // ---- Poincare ----
    {
        float z[12], e[12], io[12], ni[12];
        loadv<12,32>(z, g_Zp + o384, lane);
        expmap0v<12,32>(e, z, KPC);
        loadv<12,32>(io, iou1 + o384, lane);
        maddv<12,32>(ni, io, e, KPC);
        float ip[4], op[4], up[4];
        logmap0v<4,32>(ip, ni + 0, KPC);
        logmap0v<4,32>(op, ni + 4, KPC);
        logmap0v<4,32>(up, ni + 8, KPC);
#pragma unroll
        for (int i = 0; i < 4; i++) { ip[i] = sigf(ip[i]); op[i] = sigf(op[i]); up[i] = tanh_f(up[i]); }
        float pu[4]; pwmulv<4,32>(pu, ip, up, KPC);
        float cv[4]; loadv<4,32>(cv, g_C1 + o128, lane);
        float nc[4]; maddv<4,32>(nc, pu, cv, KPC);
        float lg[4]; logmap0v<4,32>(lg, nc, KPC);
#pragma unroll
        for (int i = 0; i < 4; i++) lg[i] = tanh_f(lg[i]);
        float nh[4]; pwmulv<4,32>(nh, op, lg, KPC);
        storev<4,32>(out + 0 * SL + o128, nh, lane);
        storev<4,32>(out + 1 * SL + o128, nc, lane);
    }
    // ---- Sphere ----
    {
        float z[12], e[12], io[12], ni[12];
        loadv<12,32>(z, g_Zs + o384, lane);
        expmap0v<12,32>(e, z, KSC);
        loadv<12,32>(io, iou2 + o384, lane);
        maddv<12,32>(ni, io, e, KSC);
        float ip[4], op[4], up[4];
        logmap0v<4,32>(ip, ni + 0, KSC);
        logmap0v<4,32>(op, ni + 4, KSC);
        logmap0v<4,32>(up, ni + 8, KSC);
#pragma unroll
        for (int i = 0; i < 4; i++) { ip[i] = sigf(ip[i]); op[i] = sigf(op[i]); up[i] = tanh_f(up[i]); }
        float pu[4]; pwmulv<4,32>(pu, ip, up, KSC);
        float cv[4]; loadv<4,32>(cv, g_C2 + o128, lane);
        float nc[4]; maddv<4,32>(nc, pu, cv, KSC);
        float lg[4]; logmap0v<4,32>(lg, nc, KSC);
#pragma unroll
        for (int i = 0; i < 4; i++) lg[i] = tanh_f(lg[i]);
        float nh[4]; pwmulv<4,32>(nh, op, lg, KSC);
        storev<4,32>(out + 2 * SL + o128, nh, lane);
        storev<4,32>(out + 3 * SL + o128, nc, lane);
    }
    // ---- Euclidean ----
    {
        float z[12], io[12];
        loadv<12,32>(z, g_Ze + o384, lane);
        loadv<12,32>(io, iou3 + o384, lane);
        float cv[4]; loadv<4,32>(cv, g_C3 + o128, lane);
        float nc[4], nh[4];
#pragma unroll
        for (int i = 0; i < 4; i++) {
            float ie = sigf(io[i] + z[i]);
            float oe = sigf(io[i + 4] + z[i + 4]);
            float ue = tanh_f(io[i + 8] + z[i + 8]);
            nc[i] = ie * ue + cv[i];
            nh[i] = oe * tanh_f(nc[i]);
        }
        storev<4,32>(out + 4 * SL + o128, nh, lane);
        storev<4,32>(out + 5 * SL + o128, nc, lane);
    }
}

// ======================= launch =======================
#define SYM(var, sym) cudaGetSymbolAddress((void**)&var, sym)

extern "C" void kernel_launch(void* const* d_in, const int* in_sizes, int n_in,
                              void* d_out, int out_size) {
    const float* x     = (const float*)d_in[0];
    const float* h1    = (const float*)d_in[1];
    const float* c1    = (const float*)d_in[2];
    const float* h2    = (const float*)d_in[3];
    const float* c2    = (const float*)d_in[4];
    const float* h3    = (const float*)d_in[5];
    const float* c3    = (const float*)d_in[6];
    const float* del_t = (const float*)d_in[7];
    const float* iou1  = (const float*)d_in[8];
    const float* iou2  = (const float*)d_in[9];
    const float* iou3  = (const float*)d_in[10];
    const float* Wq_w  = (const float*)d_in[11];
    const float* Wq_b  = (const float*)d_in[12];
    const float* Wc_w  = (const float*)d_in[13];
    const float* Wc_b  = (const float*)d_in[14];
    const float* Uf_w  = (const float*)d_in[15];
    const float* Uf_b  = (const float*)d_in[16];
    const float* Up_w  = (const float*)d_in[17];
    const float* Up_b  = (const float*)d_in[18];
    const float* Uiou_w = (const float*)d_in[19];
    const float* Uiou_b = (const float*)d_in[20];
    const float* dsc   = (const float*)d_in[21];
    const int*   nbr   = (const int*)d_in[22];
    float* out = (float*)d_out;

    float *pYup1, *pYup2, *pYup3, *pYc1, *pYc2, *pYc3, *pYuf1, *pYuf2, *pYuf3;
    float *pXQP, *pXQS, *pXQE, *pZp, *pZs, *pZe;
    SYM(pYup1, g_Yup1); SYM(pYup2, g_Yup2); SYM(pYup3, g_Yup3);
    SYM(pYc1, g_Yc1);   SYM(pYc2, g_Yc2);   SYM(pYc3, g_Yc3);
    SYM(pYuf1, g_Yuf1); SYM(pYuf2, g_Yuf2); SYM(pYuf3, g_Yuf3);
    SYM(pXQP, g_XQP);   SYM(pXQS, g_XQS);   SYM(pXQE, g_XQE);
    SYM(pZp, g_Zp);     SYM(pZs, g_Zs);     SYM(pZe, g_Ze);

    __nv_bfloat16 *pLh1h, *pLh1l, *pLh2h, *pLh2l, *pLc1h, *pLc1l, *pLc2h, *pLc2l;
    __nv_bfloat16 *pXPh, *pXPl, *pXSh, *pXSl, *pxh, *pxl, *ph3h, *ph3l, *pc3h, *pc3l;
    __nv_bfloat16 *pTPh, *pTPl, *pTSh, *pTSl, *pTEh, *pTEl;
    __nv_bfloat16 *pWqh, *pWql, *pWch, *pWcl, *pUfh, *pUfl, *pUph, *pUpl, *pUih, *pUil;
    SYM(pLh1h, b_Lh1h); SYM(pLh1l, b_Lh1l); SYM(pLh2h, b_Lh2h); SYM(pLh2l, b_Lh2l);
    SYM(pLc1h, b_Lc1h); SYM(pLc1l, b_Lc1l); SYM(pLc2h, b_Lc2h); SYM(pLc2l, b_Lc2l);
    SYM(pXPh, b_XPh);   SYM(pXPl, b_XPl);   SYM(pXSh, b_XSh);   SYM(pXSl, b_XSl);
    SYM(pxh, b_xh);     SYM(pxl, b_xl);     SYM(ph3h, b_h3h);   SYM(ph3l, b_h3l);
    SYM(pc3h, b_c3h);   SYM(pc3l, b_c3l);
    SYM(pTPh, b_TPh);   SYM(pTPl, b_TPl);   SYM(pTSh, b_TSh);   SYM(pTSl, b_TSl);
    SYM(pTEh, b_TEh);   SYM(pTEl, b_TEl);
    SYM(pWqh, b_Wqh);   SYM(pWql, b_Wql);   SYM(pWch, b_Wch);   SYM(pWcl, b_Wcl);
    SYM(pUfh, b_Ufh);   SYM(pUfl, b_Ufl);   SYM(pUph, b_Uph);   SYM(pUpl, b_Upl);
    SYM(pUih, b_Uih);   SYM(pUil, b_Uil);

    cudaFuncSetAttribute(gemm_bf, cudaFuncAttributeMaxDynamicSharedMemorySize, SMEM_BYTES);

    CvtBatch cv;
    cv.j[0] = {x,      pxh,  pxl,  NN * HH};
    cv.j[1] = {h3,     ph3h, ph3l, NN * HH};
    cv.j[2] = {c3,     pc3h, pc3l, NN * HH};
    cv.j[3] = {Wq_w,   pWqh, pWql, 128 * 128};
    cv.j[4] = {Wc_w,   pWch, pWcl, 128 * 128};
    cv.j[5] = {Uf_w,   pUfh, pUfl, 128 * 128};
    cv.j[6] = {Up_w,   pUph, pUpl, 128 * 128};
    cv.j[7] = {Uiou_w, pUih, pUil, 384 * 128};
    cvtk<<<dim3(NN * HH / 4 / 256, 8), 256>>>(cv);

    s0_prep<<<NN / 16, 256>>>(x, h1, h2, c1, c2);

    GemmBatch ga;
    ga.p[0]  = {pLh1h, pLh1l, pUph, pUpl, Up_b, pYup1};
    ga.p[1]  = {pLh2h, pLh2l, pUph, pUpl, Up_b, pYup2};
    ga.p[2]  = {ph3h,  ph3l,  pUph, pUpl, Up_b, pYup3};
    ga.p[3]  = {pLc1h, pLc1l, pWch, pWcl, Wc_b, pYc1};
    ga.p[4]  = {pLc2h, pLc2l, pWch, pWcl, Wc_b, pYc2};
    ga.p[5]  = {pc3h,  pc3l,  pWch, pWcl, Wc_b, pYc3};
    ga.p[6]  = {pLh1h, pLh1l, pUfh, pUfl, Uf_b, pYuf1};
    ga.p[7]  = {pLh2h, pLh2l, pUfh, pUfl, Uf_b, pYuf2};
    ga.p[8]  = {ph3h,  ph3l,  pUfh, pUfl, Uf_b, pYuf3};
    ga.p[9]  = {pXPh,  pXPl,  pWqh, pWql, Wq_b, pXQP};
    ga.p[10] = {pXSh,  pXSl,  pWqh, pWql, Wq_b, pXQS};
    ga.p[11] = {pxh,   pxl,   pWqh, pWql, Wq_b, pXQE};
    gemm_bf<<<dim3(NN / 128, 2, 12), 256, SMEM_BYTES>>>(ga, 128);

    s2_node<<<NN / 16, 256>>>(h1, h2, h3, c1, c2, c3, del_t, dsc);
    s3_gather<<<NN / 8, 256>>>(nbr);

    GemmBatch gb;
    gb.p[0] = {pTPh, pTPl, pUih, pUil, Uiou_b, pZp};
    gb.p[1] = {pTSh, pTSl, pUih, pUil, Uiou_b, pZs};
    gb.p[2] = {pTEh, pTEl, pUih, pUil, Uiou_b, pZe};
    for (int i = 3; i < 12; i++) gb.p[i] = gb.p[0];
    gemm_bf<<<dim3(NN / 128, 6, 3), 256, SMEM_BYTES>>>(gb, 384);

    s5_final<<<NN / 4, 128>>>(iou1, iou2, iou3, out);
}